// round 13
// baseline (speedup 1.0000x reference)
#include <cuda_runtime.h>
#include <math.h>
#include <stdint.h>

#define N_ENTC 1968
#define E_EDG  20000
#define S_DIM  16
#define D2H    256
#define H_DIM  128
#define B_DIM  8
#define T_DIM  20
#define KSEL   196
#define NCHUNK 8
#define NC_LEN 246
#define NROWS  (B_DIM * N_ENTC)
#define UPITCH 260
#define NCB    31            /* ceil(1968/64) column blocks */
#define RPAD   2048
#define SQRT_H 11.313708498984761f

__device__ float    g_qbar[B_DIM * H_DIM];
__device__ float    g_kbar[(size_t)E_EDG * H_DIM];
__device__ float    g_cf[(size_t)E_EDG * H_DIM];
__device__ float    g_w[(size_t)B_DIM * E_EDG];
__device__ float    g_att[(size_t)B_DIM * E_EDG];
__device__ unsigned g_m1[B_DIM * N_ENTC];
__device__ unsigned g_m2[B_DIM * N_ENTC];
__device__ float    g_neigh[(size_t)B_DIM * N_ENTC * H_DIM];
__device__ float    g_X[(size_t)NROWS * H_DIM];
__device__ float    g_Wt[3 * H_DIM * H_DIM];
__device__ float    g_Wb[3 * H_DIM];
__device__ float    g_Q[(size_t)B_DIM * N_ENTC * H_DIM];
__device__ float    g_Kt[(size_t)B_DIM * N_ENTC * H_DIM];
__device__ float    g_V[(size_t)B_DIM * N_ENTC * H_DIM];
__device__ float    g_P[(size_t)B_DIM * N_ENTC * N_ENTC];
__device__ float2   g_smp[(size_t)B_DIM * RPAD * NCB];   // per (row, colblock) partial (max, sumexp)
__device__ float    g_rowM[B_DIM * N_ENTC];
__device__ float    g_rowIS[B_DIM * N_ENTC];
__device__ float    g_attend[(size_t)B_DIM * KSEL * H_DIM];
__device__ double   g_imp_part[(size_t)B_DIM * NCHUNK * N_ENTC];
__device__ int      g_idx[B_DIM * KSEL];

// fused: zero neigh/m1/m2 + transpose QKV weights + stage biases
__global__ void k_zero(const float* __restrict__ Wq, const float* __restrict__ bq,
                       const float* __restrict__ Wk, const float* __restrict__ bk,
                       const float* __restrict__ Wv, const float* __restrict__ bv) {
    int i = blockIdx.x * 256 + threadIdx.x;
    if (i < B_DIM * N_ENTC * H_DIM) g_neigh[i] = 0.f;
    if (i < B_DIM * N_ENTC) { g_m1[i] = 0u; g_m2[i] = 0u; }
    if (i < 3 * H_DIM * H_DIM) {
        int which = i >> 14, r = i & 16383;
        int c = r >> 7, k = r & 127;
        const float* W = (which == 0) ? Wq : (which == 1) ? Wk : Wv;
        g_Wt[i] = W[k * H_DIM + c];
    }
    if (i < 3 * H_DIM) {
        int which = i >> 7, c = i & 127;
        const float* bb = (which == 0) ? bq : (which == 1) ? bk : bv;
        g_Wb[i] = bb[c];
    }
}

__global__ void k_qbar(const float* __restrict__ qe, const float* __restrict__ W_tok,
                       const float* __restrict__ b_tok) {
    __shared__ float qs[D2H];
    int b = blockIdx.x, tid = threadIdx.x;  // 128 thr
    #pragma unroll
    for (int k = 0; k < 2; k++) {
        int d = tid + 128 * k;
        float s = 0.f;
        #pragma unroll
        for (int t = 0; t < T_DIM; t++) s += qe[((size_t)b * T_DIM + t) * D2H + d];
        qs[d] = s * (1.f / (float)T_DIM);
    }
    __syncthreads();
    float acc = b_tok[tid];
    #pragma unroll 4
    for (int d = 0; d < D2H; d++) acc += qs[d] * W_tok[d * H_DIM + tid];
    g_qbar[b * H_DIM + tid] = acc;
}

// per-edge kernel (bit-identical kbar/cf; sacred path)
__global__ void k_edge(const float* __restrict__ ent_emb, const float* __restrict__ rel_emb,
                       const float* __restrict__ rel_mask, const int* __restrict__ src,
                       const int* __restrict__ dst, const int* __restrict__ rel_id,
                       const float* __restrict__ W_key, const float* __restrict__ b_key,
                       const float* __restrict__ W_comp, const float* __restrict__ b_comp) {
    __shared__ __align__(16) float s_u[16 * UPITCH];
    __shared__ __align__(16) float s_v[16 * UPITCH];
    __shared__ float s_mask[16][S_DIM];
    __shared__ float s_eps[16], s_msum[16];
    __shared__ int   s_src[16], s_dst[16], s_rid[16];
    __shared__ float s_wc[S_DIM];
    int tid = threadIdx.x;  // 128 thr
    int e0  = blockIdx.x * 16;
    if (tid < 16) { s_src[tid] = src[e0+tid]; s_dst[tid] = dst[e0+tid]; s_rid[tid] = rel_id[e0+tid]; }
    if (tid >= 32 && tid < 32 + S_DIM) s_wc[tid - 32] = W_comp[tid - 32];
    __syncthreads();
    for (int i = tid; i < 16 * S_DIM; i += 128) {
        int e = i / S_DIM, s = i % S_DIM;
        s_mask[e][s] = rel_mask[s_rid[e] * S_DIM + s];
    }
    __syncthreads();
    if (tid < 16) {
        float cnt = 0.f, ms = 0.f;
        #pragma unroll
        for (int s = 0; s < S_DIM; s++) { float m = s_mask[tid][s]; ms += m; cnt += (m != 0.f) ? 1.f : 0.f; }
        s_eps[tid]  = (cnt == 0.f) ? 1.f : cnt;
        s_msum[tid] = ms;
    }
    __syncthreads();
    #pragma unroll 1
    for (int it = 0; it < 8; it++) {
        int e = it * 2 + (tid >> 6);
        int f = tid & 63;
        const float4* ps = (const float4*)(ent_emb + (size_t)s_src[e] * (S_DIM * D2H));
        const float4* pd = (const float4*)(ent_emb + (size_t)s_dst[e] * (S_DIM * D2H));
        const float4* pr = (const float4*)(rel_emb + (size_t)s_rid[e] * (S_DIM * D2H));
        float4 au = make_float4(0.f, 0.f, 0.f, 0.f);
        float4 av = make_float4(0.f, 0.f, 0.f, 0.f);
        #pragma unroll
        for (int s = 0; s < S_DIM; s++) {
            float4 a = ps[s * 64 + f], r = pr[s * 64 + f], dd = pd[s * 64 + f];
            float cx = (a.x + r.x) - dd.x;
            float cy = (a.y + r.y) - dd.y;
            float cz = (a.z + r.z) - dd.z;
            float cw = (a.w + r.w) - dd.w;
            float m = s_mask[e][s], wv = s_wc[s];
            au.x += m * cx; au.y += m * cy; au.z += m * cz; au.w += m * cw;
            av.x += wv * cx; av.y += wv * cy; av.z += wv * cz; av.w += wv * cw;
        }
        *(float4*)(s_u + e * UPITCH + 4 * f) = au;
        *(float4*)(s_v + e * UPITCH + 4 * f) = av;
    }
    __syncthreads();
    float wcsum = 0.f;
    #pragma unroll
    for (int s = 0; s < S_DIM; s++) wcsum += s_wc[s];
    float ak[16], ac[16];
    #pragma unroll
    for (int e = 0; e < 16; e++) { ak[e] = 0.f; ac[e] = 0.f; }
    #pragma unroll 2
    for (int dc = 0; dc < D2H; dc += 4) {
        float w0 = W_key[(dc + 0) * H_DIM + tid];
        float w1 = W_key[(dc + 1) * H_DIM + tid];
        float w2 = W_key[(dc + 2) * H_DIM + tid];
        float w3 = W_key[(dc + 3) * H_DIM + tid];
        #pragma unroll
        for (int e = 0; e < 16; e++) {
            float4 uu = *(const float4*)(s_u + e * UPITCH + dc);
            ak[e] += uu.x * w0; ak[e] += uu.y * w1; ak[e] += uu.z * w2; ak[e] += uu.w * w3;
            float4 vv = *(const float4*)(s_v + e * UPITCH + dc);
            ac[e] += vv.x * w0; ac[e] += vv.y * w1; ac[e] += vv.z * w2; ac[e] += vv.w * w3;
        }
    }
    float bk = b_key[tid], bc = b_comp[0];
    #pragma unroll
    for (int e = 0; e < 16; e++) {
        g_kbar[(size_t)(e0+e) * H_DIM + tid] = (ak[e] + s_msum[e] * bk) / s_eps[e];
        g_cf[(size_t)(e0+e) * H_DIM + tid]   = ac[e] + wcsum * bk + bc;
    }
}

__global__ void k_w() {
    __shared__ float sq[B_DIM * H_DIM];
    int tid = threadIdx.x;  // 256 thr
    for (int i = tid; i < B_DIM * H_DIM; i += 256) sq[i] = g_qbar[i];
    __syncthreads();
    int warp = tid >> 5, lane = tid & 31;
    int e = blockIdx.x * 8 + warp;
    const float* kb = g_kbar + (size_t)e * H_DIM;
    float k0 = kb[lane], k1 = kb[lane+32], k2 = kb[lane+64], k3 = kb[lane+96];
    #pragma unroll
    for (int b = 0; b < B_DIM; b++) {
        const float* q = sq + b * H_DIM;
        float p = q[lane]*k0 + q[lane+32]*k1 + q[lane+64]*k2 + q[lane+96]*k3;
        #pragma unroll
        for (int o = 16; o; o >>= 1) p += __shfl_xor_sync(0xffffffffu, p, o);
        if (lane == 0) g_w[(size_t)b * E_EDG + e] = 0.125f * p;
    }
}

__global__ void k_attsm() {
    int b = blockIdx.x, tid = threadIdx.x;  // 1024 thr
    __shared__ float shm[32];
    __shared__ float s_mx, s_sum;
    const float* wr = g_w + (size_t)b * E_EDG;
    float mx = -INFINITY;
    for (int e = tid; e < E_EDG; e += 1024) mx = fmaxf(mx, wr[e]);
    #pragma unroll
    for (int o = 16; o; o >>= 1) mx = fmaxf(mx, __shfl_xor_sync(0xffffffffu, mx, o));
    if ((tid & 31) == 0) shm[tid >> 5] = mx;
    __syncthreads();
    if (tid == 0) { float v = shm[0]; for (int w = 1; w < 32; w++) v = fmaxf(v, shm[w]); s_mx = v; }
    __syncthreads();
    float M = s_mx, sum = 0.f;
    for (int e = tid; e < E_EDG; e += 1024) sum += expf(wr[e] - M);
    #pragma unroll
    for (int o = 16; o; o >>= 1) sum += __shfl_xor_sync(0xffffffffu, sum, o);
    if ((tid & 31) == 0) shm[tid >> 5] = sum;
    __syncthreads();
    if (tid == 0) { float v = 0.f; for (int w = 0; w < 32; w++) v += shm[w]; s_sum = v; }
    __syncthreads();
    float inv = 1.f / s_sum;
    for (int e = tid; e < E_EDG; e += 1024) g_att[(size_t)b * E_EDG + e] = expf(wr[e] - M) * inv;
}

__global__ void k_m1(const int* __restrict__ src) {
    int i = blockIdx.x * 256 + threadIdx.x;
    if (i >= B_DIM * E_EDG) return;
    int b = i / E_EDG, e = i % E_EDG;
    atomicMax(&g_m1[b * N_ENTC + src[e]], __float_as_uint(g_att[i]));
}
__global__ void k_m2(const int* __restrict__ src) {
    int i = blockIdx.x * 256 + threadIdx.x;
    if (i >= B_DIM * E_EDG) return;
    int b = i / E_EDG, e = i % E_EDG;
    unsigned v = __float_as_uint(g_att[i]);
    if (v != g_m1[b * N_ENTC + src[e]]) atomicMax(&g_m2[b * N_ENTC + src[e]], v);
}

__global__ void k_msg(const int* __restrict__ src, const int* __restrict__ dst) {
    int e = blockIdx.x, h = threadIdx.x;  // 128 thr
    float cf = g_cf[(size_t)e * H_DIM + h];
    int sn = src[e], dn = dst[e];
    #pragma unroll
    for (int b = 0; b < B_DIM; b++) {
        float a  = g_att[(size_t)b * E_EDG + e];
        float m2 = __uint_as_float(g_m2[b * N_ENTC + sn]);
        if (a >= m2) atomicAdd(&g_neigh[((size_t)b * N_ENTC + dn) * H_DIM + h], cf * a);
    }
}

__global__ void k_ln() {
    __shared__ float sx[16][H_DIM];
    int tid = threadIdx.x;  // 128 thr
    size_t r0 = (size_t)blockIdx.x * 16;
    for (int i = tid; i < 16 * H_DIM; i += 128) ((float*)sx)[i] = g_neigh[r0 * H_DIM + i];
    __syncthreads();
    int warp = tid >> 5, lane = tid & 31;
    #pragma unroll
    for (int j = 0; j < 4; j++) {
        int r = warp * 4 + j;
        float x0 = sx[r][lane], x1 = sx[r][lane+32], x2 = sx[r][lane+64], x3 = sx[r][lane+96];
        float s = x0 + x1 + x2 + x3;
        #pragma unroll
        for (int o = 16; o; o >>= 1) s += __shfl_xor_sync(0xffffffffu, s, o);
        float mu = s * (1.f / 128.f);
        float d0 = x0-mu, d1 = x1-mu, d2 = x2-mu, d3 = x3-mu;
        float q = d0*d0 + d1*d1 + d2*d2 + d3*d3;
        #pragma unroll
        for (int o = 16; o; o >>= 1) q += __shfl_xor_sync(0xffffffffu, q, o);
        float rs = rsqrtf(q * (1.f / 128.f) + 1e-5f);
        sx[r][lane] = d0*rs; sx[r][lane+32] = d1*rs; sx[r][lane+64] = d2*rs; sx[r][lane+96] = d3*rs;
    }
    __syncthreads();
    for (int i = tid; i < 16 * H_DIM; i += 128) g_X[r0 * H_DIM + i] = ((float*)sx)[i];
}

// ---------------- shared TF32 machinery ----------------
#define MMA_TF32(c, a0, a1, a2, a3, b0, b1)                                   \
    asm volatile(                                                             \
        "mma.sync.aligned.m16n8k8.row.col.f32.tf32.tf32.f32 "                 \
        "{%0,%1,%2,%3}, {%4,%5,%6,%7}, {%8,%9}, {%0,%1,%2,%3};"               \
        : "+f"(c[0]), "+f"(c[1]), "+f"(c[2]), "+f"(c[3])                      \
        : "r"(a0), "r"(a1), "r"(a2), "r"(a3), "r"(b0), "r"(b1))

__device__ __forceinline__ void tf32_split(float x, uint32_t& h, uint32_t& l) {
    asm("cvt.rna.tf32.f32 %0, %1;" : "=r"(h) : "f"(x));
    float r = x - __uint_as_float(h);
    asm("cvt.rna.tf32.f32 %0, %1;" : "=r"(l) : "f"(r));
}

__device__ __forceinline__ void cp16(uint32_t dst, const void* src, bool valid) {
    int sz = valid ? 16 : 0;
    asm volatile("cp.async.cg.shared.global [%0], [%1], 16, %2;"
                 :: "r"(dst), "l"(src), "r"(sz));
}
#define CP_COMMIT() asm volatile("cp.async.commit_group;")
#define CP_WAIT1()  asm volatile("cp.async.wait_group 1;" ::: "memory")
#define CP_WAIT0()  asm volatile("cp.async.wait_group 0;" ::: "memory")
#define PHI(kk) (((kk) & 8) | (((kk) & 3) << 1) | (((kk) >> 2) & 1))

__device__ __forceinline__ void tc_gemm_core(
    const float* __restrict__ Arows, const float* __restrict__ Brows,
    bool av0, bool av1, bool bv,
    int arow0_off, int arow1_off, int brow_off,
    float (&acc)[8][4],
    float* sQ0, float* sQ1,
    uint32_t* Kh0, uint32_t* Kl0, uint32_t* Kh1, uint32_t* Kl1)
{
    int tid = threadIdx.x;
    int warp = tid >> 5, lane = tid & 31;
    int g = lane >> 2, tig = lane & 3;
    int mr = warp * 16;
    int qrow0 = tid >> 2, seg = tid & 3;
    float* sQb[2]  = { sQ0, sQ1 };
    uint32_t* Khb[2] = { Kh0, Kh1 };
    uint32_t* Klb[2] = { Kl0, Kl1 };
    uint32_t qd0[2], qd1[2];
    #pragma unroll
    for (int bf = 0; bf < 2; bf++) {
        qd0[bf] = (uint32_t)__cvta_generic_to_shared(&sQb[bf][qrow0 * 20 + seg * 4]);
        qd1[bf] = (uint32_t)__cvta_generic_to_shared(&sQb[bf][(qrow0 + 64) * 20 + seg * 4]);
    }
    const float* qsrc0 = Arows + arow0_off;
    const float* qsrc1 = Arows + arow1_off;
    const float* ksrc  = Brows + brow_off;

    cp16(qd0[0], qsrc0, av0);
    cp16(qd1[0], qsrc1, av1);
    CP_COMMIT();
    {
        float4 kr = bv ? *(const float4*)ksrc : make_float4(0.f,0.f,0.f,0.f);
        float kvv[4] = {kr.x, kr.y, kr.z, kr.w};
        int row = tid >> 2;
        #pragma unroll
        for (int i = 0; i < 4; i++) {
            uint32_t h, l; tf32_split(kvv[i], h, l);
            int kk = seg * 4 + i;
            Khb[0][row * 20 + PHI(kk)] = h;
            Klb[0][row * 20 + PHI(kk)] = l;
        }
    }

    #pragma unroll 1
    for (int c = 0; c < 8; c++) {
        int buf = c & 1;
        float4 kr;
        if (c < 7) {
            int kc = (c + 1) * 16;
            cp16(qd0[buf ^ 1], qsrc0 + kc, av0);
            cp16(qd1[buf ^ 1], qsrc1 + kc, av1);
            CP_COMMIT();
            kr = bv ? *(const float4*)(ksrc + kc) : make_float4(0.f,0.f,0.f,0.f);
            CP_WAIT1();
        } else {
            CP_WAIT0();
        }
        __syncthreads();
        const float* Qs = sQb[buf];
        const uint32_t* KH = Khb[buf];
        const uint32_t* KL = Klb[buf];
        #pragma unroll
        for (int ks = 0; ks < 2; ks++) {
            int kb = ks * 8;
            float fa0 = Qs[(mr + g)     * 20 + kb + tig];
            float fa1 = Qs[(mr + g + 8) * 20 + kb + tig];
            float fa2 = Qs[(mr + g)     * 20 + kb + tig + 4];
            float fa3 = Qs[(mr + g + 8) * 20 + kb + tig + 4];
            uint32_t ah0, al0, ah1, al1, ah2, al2, ah3, al3;
            tf32_split(fa0, ah0, al0); tf32_split(fa1, ah1, al1);
            tf32_split(fa2, ah2, al2); tf32_split(fa3, ah3, al3);
            #pragma unroll
            for (int nt = 0; nt < 8; nt++) {
                uint2 bh = *(const uint2*)&KH[(nt * 8 + g) * 20 + kb + 2 * tig];
                uint2 bl = *(const uint2*)&KL[(nt * 8 + g) * 20 + kb + 2 * tig];
                MMA_TF32(acc[nt], al0, al1, al2, al3, bh.x, bh.y);
                MMA_TF32(acc[nt], ah0, ah1, ah2, ah3, bl.x, bl.y);
                MMA_TF32(acc[nt], ah0, ah1, ah2, ah3, bh.x, bh.y);
            }
        }
        if (c < 7) {
            int nb = buf ^ 1;
            float kvv[4] = {kr.x, kr.y, kr.z, kr.w};
            int row = tid >> 2;
            #pragma unroll
            for (int i = 0; i < 4; i++) {
                uint32_t h, l; tf32_split(kvv[i], h, l);
                int kk = seg * 4 + i;
                Khb[nb][row * 20 + PHI(kk)] = h;
                Klb[nb][row * 20 + PHI(kk)] = l;
            }
        }
        __syncthreads();
    }
}

// scores: P = sqrt(H) * Q @ K^T  + per-(row, colblock) softmax partials
__global__ void __launch_bounds__(256) k_scores_tc() {
    __shared__ __align__(16) float sQ[2][128 * 20];
    __shared__ __align__(16) uint32_t Kh[2][64 * 20], Kl[2][64 * 20];
    int b = blockIdx.z;
    int cb = blockIdx.x;
    int r0 = blockIdx.y * 128, c0 = cb * 64;
    int tid = threadIdx.x;
    int warp = tid >> 5, lane = tid & 31;
    int g = lane >> 2, tig = lane & 3;
    int mr = warp * 16;
    const float* Qb = g_Q  + (size_t)b * N_ENTC * H_DIM;
    const float* Kb = g_Kt + (size_t)b * N_ENTC * H_DIM;
    int qrow0 = tid >> 2, seg = tid & 3;
    bool av0 = (r0 + qrow0) < N_ENTC;
    bool av1 = (r0 + qrow0 + 64) < N_ENTC;
    bool bv  = (c0 + qrow0) < N_ENTC;
    int a0off = (av0 ? (r0 + qrow0)      : 0) * H_DIM + seg * 4;
    int a1off = (av1 ? (r0 + qrow0 + 64) : 0) * H_DIM + seg * 4;
    int boff  = (bv  ? (c0 + qrow0)      : 0) * H_DIM + seg * 4;
    float acc[8][4];
    #pragma unroll
    for (int nt = 0; nt < 8; nt++)
        #pragma unroll
        for (int j = 0; j < 4; j++) acc[nt][j] = 0.f;
    tc_gemm_core(Qb, Kb, av0, av1, bv, a0off, a1off, boff, acc,
                 sQ[0], sQ[1], Kh[0], Kl[0], Kh[1], Kl[1]);
    int row_a = r0 + mr + g, row_b = r0 + mr + g + 8;
    float M_a = -INFINITY, M_b = -INFINITY;
    #pragma unroll
    for (int nt = 0; nt < 8; nt++) {
        int col = c0 + nt * 8 + 2 * tig;
        bool v0 = col < N_ENTC, v1 = (col + 1) < N_ENTC;
        float va0 = acc[nt][0] * SQRT_H, va1 = acc[nt][1] * SQRT_H;
        float vb0 = acc[nt][2] * SQRT_H, vb1 = acc[nt][3] * SQRT_H;
        if (row_a < N_ENTC) {
            float* pr = g_P + ((size_t)b * N_ENTC + row_a) * N_ENTC;
            if (v0) pr[col]     = va0;
            if (v1) pr[col + 1] = va1;
        }
        if (row_b < N_ENTC) {
            float* pr = g_P + ((size_t)b * N_ENTC + row_b) * N_ENTC;
            if (v0) pr[col]     = vb0;
            if (v1) pr[col + 1] = vb1;
        }
        if (v0) { M_a = fmaxf(M_a, va0); M_b = fmaxf(M_b, vb0); }
        if (v1) { M_a = fmaxf(M_a, va1); M_b = fmaxf(M_b, vb1); }
    }
    M_a = fmaxf(M_a, __shfl_xor_sync(0xffffffffu, M_a, 1));
    M_a = fmaxf(M_a, __shfl_xor_sync(0xffffffffu, M_a, 2));
    M_b = fmaxf(M_b, __shfl_xor_sync(0xffffffffu, M_b, 1));
    M_b = fmaxf(M_b, __shfl_xor_sync(0xffffffffu, M_b, 2));
    float S_a = 0.f, S_b = 0.f;
    #pragma unroll
    for (int nt = 0; nt < 8; nt++) {
        int col = c0 + nt * 8 + 2 * tig;
        bool v0 = col < N_ENTC, v1 = (col + 1) < N_ENTC;
        if (v0) { S_a += expf(acc[nt][0] * SQRT_H - M_a); S_b += expf(acc[nt][2] * SQRT_H - M_b); }
        if (v1) { S_a += expf(acc[nt][1] * SQRT_H - M_a); S_b += expf(acc[nt][3] * SQRT_H - M_b); }
    }
    S_a += __shfl_xor_sync(0xffffffffu, S_a, 1);
    S_a += __shfl_xor_sync(0xffffffffu, S_a, 2);
    S_b += __shfl_xor_sync(0xffffffffu, S_b, 1);
    S_b += __shfl_xor_sync(0xffffffffu, S_b, 2);
    if (tig == 0) {
        if (row_a < N_ENTC) g_smp[((size_t)b * RPAD + row_a) * NCB + cb] = make_float2(M_a, S_a);
        if (row_b < N_ENTC) g_smp[((size_t)b * RPAD + row_b) * NCB + cb] = make_float2(M_b, S_b);
    }
}

// combine partials -> rowM, rowIS (deterministic ascending-cb fold; M exact)
__global__ void k_comb() {
    int i = blockIdx.x * 256 + threadIdx.x;
    if (i >= B_DIM * N_ENTC) return;
    int b = i / N_ENTC, row = i % N_ENTC;
    const float2* pp = g_smp + ((size_t)b * RPAD + row) * NCB;
    float M = -INFINITY;
    #pragma unroll 4
    for (int cb = 0; cb < NCB; cb++) M = fmaxf(M, pp[cb].x);
    float S = 0.f;
    #pragma unroll 4
    for (int cb = 0; cb < NCB; cb++) S += pp[cb].y * expf(pp[cb].x - M);
    g_rowM[i] = M;
    g_rowIS[i] = 1.f / S;
}

// QKV projection via TC
__global__ void __launch_bounds__(256) k_qkv_tc() {
    __shared__ __align__(16) float sQ[2][128 * 20];
    __shared__ __align__(16) uint32_t Kh[2][64 * 20], Kl[2][64 * 20];
    int which = blockIdx.x >> 1;
    int c0 = (blockIdx.x & 1) * 64;
    int r0 = blockIdx.y * 128;
    int tid = threadIdx.x;
    int warp = tid >> 5, lane = tid & 31;
    int g = lane >> 2, tig = lane & 3;
    int mr = warp * 16;
    const float* Wt = g_Wt + which * H_DIM * H_DIM;
    int qrow0 = tid >> 2, seg = tid & 3;
    int a0off = (r0 + qrow0) * H_DIM + seg * 4;
    int a1off = (r0 + qrow0 + 64) * H_DIM + seg * 4;
    int boff  = (c0 + qrow0) * H_DIM + seg * 4;
    float acc[8][4];
    #pragma unroll
    for (int nt = 0; nt < 8; nt++)
        #pragma unroll
        for (int j = 0; j < 4; j++) acc[nt][j] = 0.f;
    tc_gemm_core(g_X, Wt, true, true, true, a0off, a1off, boff, acc,
                 sQ[0], sQ[1], Kh[0], Kl[0], Kh[1], Kl[1]);
    float* outp = (which == 0) ? g_Q : (which == 1) ? g_Kt : g_V;
    #pragma unroll
    for (int nt = 0; nt < 8; nt++) {
        int col = c0 + nt * 8 + 2 * tig;
        float b0 = g_Wb[which * H_DIM + col];
        float b1 = g_Wb[which * H_DIM + col + 1];
        int row_a = r0 + mr + g, row_b = r0 + mr + g + 8;
        outp[(size_t)row_a * H_DIM + col]     = acc[nt][0] + b0;
        outp[(size_t)row_a * H_DIM + col + 1] = acc[nt][1] + b1;
        outp[(size_t)row_b * H_DIM + col]     = acc[nt][2] + b0;
        outp[(size_t)row_b * H_DIM + col + 1] = acc[nt][3] + b1;
    }
}

// importance stage 1 over raw P, normalizing on the fly (deterministic)
__global__ void k_imp_part() {
    int m = blockIdx.x * 256 + threadIdx.x;
    int nc = blockIdx.y, b = blockIdx.z;
    if (m >= N_ENTC) return;
    const float* base = g_P + (size_t)b * N_ENTC * N_ENTC + m;
    const float* rM  = g_rowM  + b * N_ENTC;
    const float* rIS = g_rowIS + b * N_ENTC;
    int n0 = nc * NC_LEN, n1 = n0 + NC_LEN;
    double a0 = 0.0, a1 = 0.0, a2 = 0.0, a3 = 0.0;
    int n = n0;
    for (; n + 4 <= n1; n += 4) {
        a0 += (double)(expf(base[(size_t)(n+0) * N_ENTC] - rM[n+0]) * rIS[n+0]);
        a1 += (double)(expf(base[(size_t)(n+1) * N_ENTC] - rM[n+1]) * rIS[n+1]);
        a2 += (double)(expf(base[(size_t)(n+2) * N_ENTC] - rM[n+2]) * rIS[n+2]);
        a3 += (double)(expf(base[(size_t)(n+3) * N_ENTC] - rM[n+3]) * rIS[n+3]);
    }
    for (; n < n1; n++) a0 += (double)(expf(base[(size_t)n * N_ENTC] - rM[n]) * rIS[n]);
    g_imp_part[((size_t)b * NCHUNK + nc) * N_ENTC + m] = (a0 + a1) + (a2 + a3);
}

// importance stage 2 + top-K rank
__global__ void k_topk() {
    __shared__ float sv[N_ENTC];
    int b = blockIdx.y, tid = threadIdx.x;  // 256 thr
    const double* pp = g_imp_part + (size_t)b * NCHUNK * N_ENTC;
    for (int m = tid; m < N_ENTC; m += 256) {
        double s = 0.0;
        #pragma unroll
        for (int c = 0; c < NCHUNK; c++) s += pp[(size_t)c * N_ENTC + m];
        sv[m] = (float)(s * (1.0 / (double)N_ENTC));
    }
    __syncthreads();
    int m = blockIdx.x * 256 + tid;
    if (m >= N_ENTC) return;
    float vm = sv[m];
    int rank = 0;
    for (int n = 0; n < N_ENTC; n++) {
        float vn = sv[n];
        rank += (vn > vm) ? 1 : 0;
        rank += (vn == vm && n < m) ? 1 : 0;
    }
    if (rank < KSEL) g_idx[b * KSEL + rank] = m;
}

// attended rows for selected indices; normalize raw P on load
__global__ void k_attend_sel() {
    __shared__ __align__(16) float sP[32][68];
    __shared__ __align__(16) float sV[32][132];
    __shared__ int s_idx[64];
    __shared__ float s_M[64], s_IS[64];
    int b = blockIdx.y;
    int r0 = blockIdx.x * 64;
    int tid = threadIdx.x, tx = tid & 15, ty = tid >> 4;  // 256 thr
    if (tid < 64) {
        int sr = r0 + tid;
        int ridx = (sr < KSEL) ? g_idx[b * KSEL + sr] : 0;
        s_idx[tid] = ridx;
        s_M[tid]  = g_rowM[b * N_ENTC + ridx];
        s_IS[tid] = g_rowIS[b * N_ENTC + ridx];
    }
    __syncthreads();
    const float* Pb = g_P + (size_t)b * N_ENTC * N_ENTC;
    const float* Vb = g_V + (size_t)b * N_ENTC * H_DIM;
    float acc[2][4][4];
    #pragma unroll
    for (int h = 0; h < 2; h++)
        #pragma unroll
        for (int i = 0; i < 4; i++)
            #pragma unroll
            for (int j = 0; j < 4; j++) acc[h][i][j] = 0.f;
    for (int k0 = 0; k0 < N_ENTC; k0 += 32) {
        #pragma unroll
        for (int p = 0; p < 8; p++) {
            int lin = tid + 256 * p;
            int kk = lin & 31, row = lin >> 5;
            int gk = k0 + kk;
            bool rv = (r0 + row) < KSEL;
            sP[kk][row] = (rv && gk < N_ENTC)
                ? expf(Pb[(size_t)s_idx[row] * N_ENTC + gk] - s_M[row]) * s_IS[row] : 0.f;
        }
        #pragma unroll
        for (int p = 0; p < 16; p++) {
            int lin = tid + 256 * p;
            int col = lin & 127, kk2 = lin >> 7;
            int gk2 = k0 + kk2;
            sV[kk2][col] = (gk2 < N_ENTC) ? Vb[(size_t)gk2 * H_DIM + col] : 0.f;
        }
        __syncthreads();
        #pragma unroll
        for (int kk = 0; kk < 32; kk++) {
            float4 a = *(const float4*)&sP[kk][ty * 4];
            float ar[4] = {a.x, a.y, a.z, a.w};
            #pragma unroll
            for (int h = 0; h < 2; h++) {
                float4 bb = *(const float4*)&sV[kk][h * 64 + tx * 4];
                float br[4] = {bb.x, bb.y, bb.z, bb.w};
                #pragma unroll
                for (int i = 0; i < 4; i++)
                    #pragma unroll
                    for (int j = 0; j < 4; j++) acc[h][i][j] += ar[i] * br[j];
            }
        }
        __syncthreads();
    }
    #pragma unroll
    for (int h = 0; h < 2; h++)
        #pragma unroll
        for (int i = 0; i < 4; i++) {
            int gr = r0 + ty * 4 + i;
            if (gr >= KSEL) continue;
            #pragma unroll
            for (int j = 0; j < 4; j++) {
                int gc = h * 64 + tx * 4 + j;
                g_attend[((size_t)b * KSEL + gr) * H_DIM + gc] = acc[h][i][j];
            }
        }
}

// out[b,k,:] = tanh(attend_compact[b,k,:] @ W_kg + b_kg)
__global__ void k_sel(const float* __restrict__ W_kg, const float* __restrict__ b_kg,
                      float* __restrict__ out) {
    __shared__ float sx[16][H_DIM];
    int tid = threadIdx.x;  // 128 thr
    int b = blockIdx.y;
    int kt = blockIdx.x * 16;
    int nvalid = min(16, KSEL - kt);
    for (int r = 0; r < nvalid; r++)
        sx[r][tid] = g_attend[((size_t)b * KSEL + kt + r) * H_DIM + tid];
    __syncthreads();
    float acc[16];
    #pragma unroll
    for (int r = 0; r < 16; r++) acc[r] = 0.f;
    #pragma unroll 2
    for (int d = 0; d < H_DIM; d++) {
        float w = W_kg[d * H_DIM + tid];
        #pragma unroll
        for (int r = 0; r < 16; r++) acc[r] += sx[r][d] * w;
    }
    float bb = b_kg[tid];
    for (int r = 0; r < nvalid; r++)
        out[((size_t)b * KSEL + kt + r) * H_DIM + tid] = tanhf(acc[r] + bb);
}

extern "C" void kernel_launch(void* const* d_in, const int* in_sizes, int n_in,
                              void* d_out, int out_size) {
    const float *ent_emb, *rel_emb, *rel_mask, *qe;
    const float *W_tok, *b_tok, *W_key, *b_key, *W_comp, *b_comp;
    const float *Wq, *bq, *Wk, *bk, *Wv, *bv, *W_kg, *b_kg;
    const int *src, *dst, *rel_id;
    if (in_sizes[5] == E_EDG) {
        ent_emb = (const float*)d_in[0];  rel_emb = (const float*)d_in[1];
        rel_mask = (const float*)d_in[3]; qe = (const float*)d_in[4];
        src = (const int*)d_in[5]; dst = (const int*)d_in[6]; rel_id = (const int*)d_in[7];
        W_tok = (const float*)d_in[8];  b_tok = (const float*)d_in[9];
        W_key = (const float*)d_in[10]; b_key = (const float*)d_in[11];
        W_comp = (const float*)d_in[12]; b_comp = (const float*)d_in[13];
        Wq = (const float*)d_in[14]; bq = (const float*)d_in[15];
        Wk = (const float*)d_in[16]; bk = (const float*)d_in[17];
        Wv = (const float*)d_in[18]; bv = (const float*)d_in[19];
        W_kg = (const float*)d_in[20]; b_kg = (const float*)d_in[21];
    } else {
        ent_emb = (const float*)d_in[0];  rel_emb = (const float*)d_in[1];
        rel_mask = (const float*)d_in[3]; qe = (const float*)d_in[4];
        W_tok = (const float*)d_in[5];  b_tok = (const float*)d_in[6];
        W_key = (const float*)d_in[7];  b_key = (const float*)d_in[8];
        W_comp = (const float*)d_in[9]; b_comp = (const float*)d_in[10];
        Wq = (const float*)d_in[11]; bq = (const float*)d_in[12];
        Wk = (const float*)d_in[13]; bk = (const float*)d_in[14];
        Wv = (const float*)d_in[15]; bv = (const float*)d_in[16];
        W_kg = (const float*)d_in[17]; b_kg = (const float*)d_in[18];
        src = (const int*)d_in[19]; dst = (const int*)d_in[20]; rel_id = (const int*)d_in[21];
    }
    float* out = (float*)d_out;

    k_zero<<<(B_DIM * N_ENTC * H_DIM + 255) / 256, 256>>>(Wq, bq, Wk, bk, Wv, bv);
    k_qbar<<<B_DIM, 128>>>(qe, W_tok, b_tok);
    k_edge<<<E_EDG / 16, 128>>>(ent_emb, rel_emb, rel_mask, src, dst, rel_id,
                                 W_key, b_key, W_comp, b_comp);
    k_w<<<E_EDG / 8, 256>>>();
    k_attsm<<<B_DIM, 1024>>>();
    k_m1<<<(B_DIM * E_EDG + 255) / 256, 256>>>(src);
    k_m2<<<(B_DIM * E_EDG + 255) / 256, 256>>>(src);
    k_msg<<<E_EDG, 128>>>(src, dst);
    k_ln<<<NROWS / 16, 128>>>();
    {
        dim3 g(6, NROWS / 128);
        k_qkv_tc<<<g, 256>>>();
    }
    {
        dim3 g(NCB, (N_ENTC + 127) / 128, B_DIM);
        k_scores_tc<<<g, 256>>>();
    }
    k_comb<<<(B_DIM * N_ENTC + 255) / 256, 256>>>();
    {
        dim3 g((N_ENTC + 255) / 256, NCHUNK, B_DIM);
        k_imp_part<<<g, 256>>>();
    }
    {
        dim3 g((N_ENTC + 255) / 256, B_DIM);
        k_topk<<<g, 256>>>();
    }
    {
        dim3 g((KSEL + 63) / 64, B_DIM);
        k_attend_sel<<<g, 256>>>();
    }
    {
        dim3 g((KSEL + 15) / 16, B_DIM);
        k_sel<<<g, 128>>>(W_kg, b_kg, out);
    }
}

// round 14
// speedup vs baseline: 1.0446x; 1.0446x over previous
#include <cuda_runtime.h>
#include <math.h>
#include <stdint.h>

#define N_ENTC 1968
#define E_EDG  20000
#define S_DIM  16
#define D2H    256
#define H_DIM  128
#define B_DIM  8
#define T_DIM  20
#define KSEL   196
#define NCHUNK 8
#define NC_LEN 246
#define NROWS  (B_DIM * N_ENTC)
#define UPITCH 260
#define SQRT_H 11.313708498984761f

__device__ float    g_qbar[B_DIM * H_DIM];
__device__ float    g_kbar[(size_t)E_EDG * H_DIM];
__device__ float    g_cf[(size_t)E_EDG * H_DIM];
__device__ float    g_w[(size_t)B_DIM * E_EDG];
__device__ float    g_att[(size_t)B_DIM * E_EDG];
__device__ unsigned g_m1[B_DIM * N_ENTC];
__device__ unsigned g_m2[B_DIM * N_ENTC];
__device__ float    g_neigh[(size_t)B_DIM * N_ENTC * H_DIM];
__device__ float    g_X[(size_t)NROWS * H_DIM];
__device__ float    g_Wt[3 * H_DIM * H_DIM];
__device__ float    g_Wb[3 * H_DIM];
__device__ float    g_Q[(size_t)B_DIM * N_ENTC * H_DIM];
__device__ float    g_Kt[(size_t)B_DIM * N_ENTC * H_DIM];
__device__ float    g_V[(size_t)B_DIM * N_ENTC * H_DIM];
__device__ float    g_P[(size_t)B_DIM * N_ENTC * N_ENTC];
__device__ float    g_attend[(size_t)B_DIM * KSEL * H_DIM];
__device__ double   g_imp_part[(size_t)B_DIM * NCHUNK * N_ENTC];
__device__ int      g_idx[B_DIM * KSEL];

// fused: zero neigh/m1/m2 + transpose QKV weights + stage biases
__global__ void k_zero(const float* __restrict__ Wq, const float* __restrict__ bq,
                       const float* __restrict__ Wk, const float* __restrict__ bk,
                       const float* __restrict__ Wv, const float* __restrict__ bv) {
    int i = blockIdx.x * 256 + threadIdx.x;
    if (i < B_DIM * N_ENTC * H_DIM) g_neigh[i] = 0.f;
    if (i < B_DIM * N_ENTC) { g_m1[i] = 0u; g_m2[i] = 0u; }
    if (i < 3 * H_DIM * H_DIM) {
        int which = i >> 14, r = i & 16383;
        int c = r >> 7, k = r & 127;
        const float* W = (which == 0) ? Wq : (which == 1) ? Wk : Wv;
        g_Wt[i] = W[k * H_DIM + c];
    }
    if (i < 3 * H_DIM) {
        int which = i >> 7, c = i & 127;
        const float* bb = (which == 0) ? bq : (which == 1) ? bk : bv;
        g_Wb[i] = bb[c];
    }
}

// qbar[b] = (mean_t question[b]) @ W_tok + b_tok
__global__ void k_qbar(const float* __restrict__ qe, const float* __restrict__ W_tok,
                       const float* __restrict__ b_tok) {
    __shared__ float qs[D2H];
    int b = blockIdx.x, tid = threadIdx.x;  // 128 thr
    #pragma unroll
    for (int k = 0; k < 2; k++) {
        int d = tid + 128 * k;
        float s = 0.f;
        #pragma unroll
        for (int t = 0; t < T_DIM; t++) s += qe[((size_t)b * T_DIM + t) * D2H + d];
        qs[d] = s * (1.f / (float)T_DIM);
    }
    __syncthreads();
    float acc = b_tok[tid];
    #pragma unroll 4
    for (int d = 0; d < D2H; d++) acc += qs[d] * W_tok[d * H_DIM + tid];
    g_qbar[b * H_DIM + tid] = acc;
}

// per-edge kernel: u/v staged [e][d]; FMA sequence bit-identical to prior rounds.
__global__ void k_edge(const float* __restrict__ ent_emb, const float* __restrict__ rel_emb,
                       const float* __restrict__ rel_mask, const int* __restrict__ src,
                       const int* __restrict__ dst, const int* __restrict__ rel_id,
                       const float* __restrict__ W_key, const float* __restrict__ b_key,
                       const float* __restrict__ W_comp, const float* __restrict__ b_comp) {
    __shared__ __align__(16) float s_u[16 * UPITCH];
    __shared__ __align__(16) float s_v[16 * UPITCH];
    __shared__ float s_mask[16][S_DIM];
    __shared__ float s_eps[16], s_msum[16];
    __shared__ int   s_src[16], s_dst[16], s_rid[16];
    __shared__ float s_wc[S_DIM];
    int tid = threadIdx.x;  // 128 thr
    int e0  = blockIdx.x * 16;
    if (tid < 16) { s_src[tid] = src[e0+tid]; s_dst[tid] = dst[e0+tid]; s_rid[tid] = rel_id[e0+tid]; }
    if (tid >= 32 && tid < 32 + S_DIM) s_wc[tid - 32] = W_comp[tid - 32];
    __syncthreads();
    for (int i = tid; i < 16 * S_DIM; i += 128) {
        int e = i / S_DIM, s = i % S_DIM;
        s_mask[e][s] = rel_mask[s_rid[e] * S_DIM + s];
    }
    __syncthreads();
    if (tid < 16) {
        float cnt = 0.f, ms = 0.f;
        #pragma unroll
        for (int s = 0; s < S_DIM; s++) { float m = s_mask[tid][s]; ms += m; cnt += (m != 0.f) ? 1.f : 0.f; }
        s_eps[tid]  = (cnt == 0.f) ? 1.f : cnt;
        s_msum[tid] = ms;
    }
    __syncthreads();
    #pragma unroll 1
    for (int it = 0; it < 8; it++) {
        int e = it * 2 + (tid >> 6);
        int f = tid & 63;
        const float4* ps = (const float4*)(ent_emb + (size_t)s_src[e] * (S_DIM * D2H));
        const float4* pd = (const float4*)(ent_emb + (size_t)s_dst[e] * (S_DIM * D2H));
        const float4* pr = (const float4*)(rel_emb + (size_t)s_rid[e] * (S_DIM * D2H));
        float4 au = make_float4(0.f, 0.f, 0.f, 0.f);
        float4 av = make_float4(0.f, 0.f, 0.f, 0.f);
        #pragma unroll
        for (int s = 0; s < S_DIM; s++) {
            float4 a = ps[s * 64 + f], r = pr[s * 64 + f], dd = pd[s * 64 + f];
            float cx = (a.x + r.x) - dd.x;
            float cy = (a.y + r.y) - dd.y;
            float cz = (a.z + r.z) - dd.z;
            float cw = (a.w + r.w) - dd.w;
            float m = s_mask[e][s], wv = s_wc[s];
            au.x += m * cx; au.y += m * cy; au.z += m * cz; au.w += m * cw;
            av.x += wv * cx; av.y += wv * cy; av.z += wv * cz; av.w += wv * cw;
        }
        *(float4*)(s_u + e * UPITCH + 4 * f) = au;
        *(float4*)(s_v + e * UPITCH + 4 * f) = av;
    }
    __syncthreads();
    float wcsum = 0.f;
    #pragma unroll
    for (int s = 0; s < S_DIM; s++) wcsum += s_wc[s];
    float ak[16], ac[16];
    #pragma unroll
    for (int e = 0; e < 16; e++) { ak[e] = 0.f; ac[e] = 0.f; }
    #pragma unroll 2
    for (int dc = 0; dc < D2H; dc += 4) {
        float w0 = W_key[(dc + 0) * H_DIM + tid];
        float w1 = W_key[(dc + 1) * H_DIM + tid];
        float w2 = W_key[(dc + 2) * H_DIM + tid];
        float w3 = W_key[(dc + 3) * H_DIM + tid];
        #pragma unroll
        for (int e = 0; e < 16; e++) {
            float4 uu = *(const float4*)(s_u + e * UPITCH + dc);
            ak[e] += uu.x * w0; ak[e] += uu.y * w1; ak[e] += uu.z * w2; ak[e] += uu.w * w3;
            float4 vv = *(const float4*)(s_v + e * UPITCH + dc);
            ac[e] += vv.x * w0; ac[e] += vv.y * w1; ac[e] += vv.z * w2; ac[e] += vv.w * w3;
        }
    }
    float bk = b_key[tid], bc = b_comp[0];
    #pragma unroll
    for (int e = 0; e < 16; e++) {
        g_kbar[(size_t)(e0+e) * H_DIM + tid] = (ak[e] + s_msum[e] * bk) / s_eps[e];
        g_cf[(size_t)(e0+e) * H_DIM + tid]   = ac[e] + wcsum * bk + bc;
    }
}

// w[b,e] = 0.125 * qbar[b] . kbar[e]
__global__ void k_w() {
    __shared__ float sq[B_DIM * H_DIM];
    int tid = threadIdx.x;  // 256 thr
    for (int i = tid; i < B_DIM * H_DIM; i += 256) sq[i] = g_qbar[i];
    __syncthreads();
    int warp = tid >> 5, lane = tid & 31;
    int e = blockIdx.x * 8 + warp;
    const float* kb = g_kbar + (size_t)e * H_DIM;
    float k0 = kb[lane], k1 = kb[lane+32], k2 = kb[lane+64], k3 = kb[lane+96];
    #pragma unroll
    for (int b = 0; b < B_DIM; b++) {
        const float* q = sq + b * H_DIM;
        float p = q[lane]*k0 + q[lane+32]*k1 + q[lane+64]*k2 + q[lane+96]*k3;
        #pragma unroll
        for (int o = 16; o; o >>= 1) p += __shfl_xor_sync(0xffffffffu, p, o);
        if (lane == 0) g_w[(size_t)b * E_EDG + e] = 0.125f * p;
    }
}

__global__ void k_attsm() {
    int b = blockIdx.x, tid = threadIdx.x;  // 1024 thr
    __shared__ float shm[32];
    __shared__ float s_mx, s_sum;
    const float* wr = g_w + (size_t)b * E_EDG;
    float mx = -INFINITY;
    for (int e = tid; e < E_EDG; e += 1024) mx = fmaxf(mx, wr[e]);
    #pragma unroll
    for (int o = 16; o; o >>= 1) mx = fmaxf(mx, __shfl_xor_sync(0xffffffffu, mx, o));
    if ((tid & 31) == 0) shm[tid >> 5] = mx;
    __syncthreads();
    if (tid == 0) { float v = shm[0]; for (int w = 1; w < 32; w++) v = fmaxf(v, shm[w]); s_mx = v; }
    __syncthreads();
    float M = s_mx, sum = 0.f;
    for (int e = tid; e < E_EDG; e += 1024) sum += expf(wr[e] - M);
    #pragma unroll
    for (int o = 16; o; o >>= 1) sum += __shfl_xor_sync(0xffffffffu, sum, o);
    if ((tid & 31) == 0) shm[tid >> 5] = sum;
    __syncthreads();
    if (tid == 0) { float v = 0.f; for (int w = 0; w < 32; w++) v += shm[w]; s_sum = v; }
    __syncthreads();
    float inv = 1.f / s_sum;
    for (int e = tid; e < E_EDG; e += 1024) g_att[(size_t)b * E_EDG + e] = expf(wr[e] - M) * inv;
}

__global__ void k_m1(const int* __restrict__ src) {
    int i = blockIdx.x * 256 + threadIdx.x;
    if (i >= B_DIM * E_EDG) return;
    int b = i / E_EDG, e = i % E_EDG;
    atomicMax(&g_m1[b * N_ENTC + src[e]], __float_as_uint(g_att[i]));
}
__global__ void k_m2(const int* __restrict__ src) {
    int i = blockIdx.x * 256 + threadIdx.x;
    if (i >= B_DIM * E_EDG) return;
    int b = i / E_EDG, e = i % E_EDG;
    unsigned v = __float_as_uint(g_att[i]);
    if (v != g_m1[b * N_ENTC + src[e]]) atomicMax(&g_m2[b * N_ENTC + src[e]], v);
}

__global__ void k_msg(const int* __restrict__ src, const int* __restrict__ dst) {
    int e = blockIdx.x, h = threadIdx.x;  // 128 thr
    float cf = g_cf[(size_t)e * H_DIM + h];
    int sn = src[e], dn = dst[e];
    #pragma unroll
    for (int b = 0; b < B_DIM; b++) {
        float a  = g_att[(size_t)b * E_EDG + e];
        float m2 = __uint_as_float(g_m2[b * N_ENTC + sn]);
        if (a >= m2) atomicAdd(&g_neigh[((size_t)b * N_ENTC + dn) * H_DIM + h], cf * a);
    }
}

// LayerNorm (bit-identical), writes g_X
__global__ void k_ln() {
    __shared__ float sx[16][H_DIM];
    int tid = threadIdx.x;  // 128 thr
    size_t r0 = (size_t)blockIdx.x * 16;
    for (int i = tid; i < 16 * H_DIM; i += 128) ((float*)sx)[i] = g_neigh[r0 * H_DIM + i];
    __syncthreads();
    int warp = tid >> 5, lane = tid & 31;
    #pragma unroll
    for (int j = 0; j < 4; j++) {
        int r = warp * 4 + j;
        float x0 = sx[r][lane], x1 = sx[r][lane+32], x2 = sx[r][lane+64], x3 = sx[r][lane+96];
        float s = x0 + x1 + x2 + x3;
        #pragma unroll
        for (int o = 16; o; o >>= 1) s += __shfl_xor_sync(0xffffffffu, s, o);
        float mu = s * (1.f / 128.f);
        float d0 = x0-mu, d1 = x1-mu, d2 = x2-mu, d3 = x3-mu;
        float q = d0*d0 + d1*d1 + d2*d2 + d3*d3;
        #pragma unroll
        for (int o = 16; o; o >>= 1) q += __shfl_xor_sync(0xffffffffu, q, o);
        float rs = rsqrtf(q * (1.f / 128.f) + 1e-5f);
        sx[r][lane] = d0*rs; sx[r][lane+32] = d1*rs; sx[r][lane+64] = d2*rs; sx[r][lane+96] = d3*rs;
    }
    __syncthreads();
    for (int i = tid; i < 16 * H_DIM; i += 128) g_X[r0 * H_DIM + i] = ((float*)sx)[i];
}

// ---------------- shared TF32 machinery ----------------
#define MMA_TF32(c, a0, a1, a2, a3, b0, b1)                                   \
    asm volatile(                                                             \
        "mma.sync.aligned.m16n8k8.row.col.f32.tf32.tf32.f32 "                 \
        "{%0,%1,%2,%3}, {%4,%5,%6,%7}, {%8,%9}, {%0,%1,%2,%3};"               \
        : "+f"(c[0]), "+f"(c[1]), "+f"(c[2]), "+f"(c[3])                      \
        : "r"(a0), "r"(a1), "r"(a2), "r"(a3), "r"(b0), "r"(b1))

__device__ __forceinline__ void tf32_split(float x, uint32_t& h, uint32_t& l) {
    asm("cvt.rna.tf32.f32 %0, %1;" : "=r"(h) : "f"(x));
    float r = x - __uint_as_float(h);
    asm("cvt.rna.tf32.f32 %0, %1;" : "=r"(l) : "f"(r));
}

__device__ __forceinline__ void cp16(uint32_t dst, const void* src, bool valid) {
    int sz = valid ? 16 : 0;
    asm volatile("cp.async.cg.shared.global [%0], [%1], 16, %2;"
                 :: "r"(dst), "l"(src), "r"(sz));
}
#define CP_COMMIT() asm volatile("cp.async.commit_group;")
#define CP_WAIT1()  asm volatile("cp.async.wait_group 1;" ::: "memory")
#define CP_WAIT0()  asm volatile("cp.async.wait_group 0;" ::: "memory")
#define PHI(kk) (((kk) & 8) | (((kk) & 3) << 1) | (((kk) >> 2) & 1))

__device__ __forceinline__ void tc_gemm_core(
    const float* __restrict__ Arows, const float* __restrict__ Brows,
    bool av0, bool av1, bool bv,
    int arow0_off, int arow1_off, int brow_off,
    float (&acc)[8][4],
    float* sQ0, float* sQ1,
    uint32_t* Kh0, uint32_t* Kl0, uint32_t* Kh1, uint32_t* Kl1)
{
    int tid = threadIdx.x;
    int warp = tid >> 5, lane = tid & 31;
    int g = lane >> 2, tig = lane & 3;
    int mr = warp * 16;
    int qrow0 = tid >> 2, seg = tid & 3;
    float* sQb[2]  = { sQ0, sQ1 };
    uint32_t* Khb[2] = { Kh0, Kh1 };
    uint32_t* Klb[2] = { Kl0, Kl1 };
    uint32_t qd0[2], qd1[2];
    #pragma unroll
    for (int bf = 0; bf < 2; bf++) {
        qd0[bf] = (uint32_t)__cvta_generic_to_shared(&sQb[bf][qrow0 * 20 + seg * 4]);
        qd1[bf] = (uint32_t)__cvta_generic_to_shared(&sQb[bf][(qrow0 + 64) * 20 + seg * 4]);
    }
    const float* qsrc0 = Arows + arow0_off;
    const float* qsrc1 = Arows + arow1_off;
    const float* ksrc  = Brows + brow_off;

    cp16(qd0[0], qsrc0, av0);
    cp16(qd1[0], qsrc1, av1);
    CP_COMMIT();
    {
        float4 kr = bv ? *(const float4*)ksrc : make_float4(0.f,0.f,0.f,0.f);
        float kvv[4] = {kr.x, kr.y, kr.z, kr.w};
        int row = tid >> 2;
        #pragma unroll
        for (int i = 0; i < 4; i++) {
            uint32_t h, l; tf32_split(kvv[i], h, l);
            int kk = seg * 4 + i;
            Khb[0][row * 20 + PHI(kk)] = h;
            Klb[0][row * 20 + PHI(kk)] = l;
        }
    }

    #pragma unroll 1
    for (int c = 0; c < 8; c++) {
        int buf = c & 1;
        float4 kr;
        if (c < 7) {
            int kc = (c + 1) * 16;
            cp16(qd0[buf ^ 1], qsrc0 + kc, av0);
            cp16(qd1[buf ^ 1], qsrc1 + kc, av1);
            CP_COMMIT();
            kr = bv ? *(const float4*)(ksrc + kc) : make_float4(0.f,0.f,0.f,0.f);
            CP_WAIT1();
        } else {
            CP_WAIT0();
        }
        __syncthreads();
        const float* Qs = sQb[buf];
        const uint32_t* KH = Khb[buf];
        const uint32_t* KL = Klb[buf];
        #pragma unroll
        for (int ks = 0; ks < 2; ks++) {
            int kb = ks * 8;
            float fa0 = Qs[(mr + g)     * 20 + kb + tig];
            float fa1 = Qs[(mr + g + 8) * 20 + kb + tig];
            float fa2 = Qs[(mr + g)     * 20 + kb + tig + 4];
            float fa3 = Qs[(mr + g + 8) * 20 + kb + tig + 4];
            uint32_t ah0, al0, ah1, al1, ah2, al2, ah3, al3;
            tf32_split(fa0, ah0, al0); tf32_split(fa1, ah1, al1);
            tf32_split(fa2, ah2, al2); tf32_split(fa3, ah3, al3);
            #pragma unroll
            for (int nt = 0; nt < 8; nt++) {
                uint2 bh = *(const uint2*)&KH[(nt * 8 + g) * 20 + kb + 2 * tig];
                uint2 bl = *(const uint2*)&KL[(nt * 8 + g) * 20 + kb + 2 * tig];
                MMA_TF32(acc[nt], al0, al1, al2, al3, bh.x, bh.y);
                MMA_TF32(acc[nt], ah0, ah1, ah2, ah3, bl.x, bl.y);
                MMA_TF32(acc[nt], ah0, ah1, ah2, ah3, bh.x, bh.y);
            }
        }
        if (c < 7) {
            int nb = buf ^ 1;
            float kvv[4] = {kr.x, kr.y, kr.z, kr.w};
            int row = tid >> 2;
            #pragma unroll
            for (int i = 0; i < 4; i++) {
                uint32_t h, l; tf32_split(kvv[i], h, l);
                int kk = seg * 4 + i;
                Khb[nb][row * 20 + PHI(kk)] = h;
                Klb[nb][row * 20 + PHI(kk)] = l;
            }
        }
        __syncthreads();
    }
}

// scores: P = sqrt(H) * Q @ K^T
__global__ void __launch_bounds__(256) k_scores_tc() {
    __shared__ __align__(16) float sQ[2][128 * 20];
    __shared__ __align__(16) uint32_t Kh[2][64 * 20], Kl[2][64 * 20];
    int b = blockIdx.z;
    int r0 = blockIdx.y * 128, c0 = blockIdx.x * 64;
    int tid = threadIdx.x;
    int warp = tid >> 5, lane = tid & 31;
    int g = lane >> 2, tig = lane & 3;
    int mr = warp * 16;
    const float* Qb = g_Q  + (size_t)b * N_ENTC * H_DIM;
    const float* Kb = g_Kt + (size_t)b * N_ENTC * H_DIM;
    int qrow0 = tid >> 2, seg = tid & 3;
    bool av0 = (r0 + qrow0) < N_ENTC;
    bool av1 = (r0 + qrow0 + 64) < N_ENTC;
    bool bv  = (c0 + qrow0) < N_ENTC;
    int a0off = (av0 ? (r0 + qrow0)      : 0) * H_DIM + seg * 4;
    int a1off = (av1 ? (r0 + qrow0 + 64) : 0) * H_DIM + seg * 4;
    int boff  = (bv  ? (c0 + qrow0)      : 0) * H_DIM + seg * 4;
    float acc[8][4];
    #pragma unroll
    for (int nt = 0; nt < 8; nt++)
        #pragma unroll
        for (int j = 0; j < 4; j++) acc[nt][j] = 0.f;
    tc_gemm_core(Qb, Kb, av0, av1, bv, a0off, a1off, boff, acc,
                 sQ[0], sQ[1], Kh[0], Kl[0], Kh[1], Kl[1]);
    #pragma unroll
    for (int nt = 0; nt < 8; nt++) {
        int col = c0 + nt * 8 + 2 * tig;
        int row_a = r0 + mr + g, row_b = r0 + mr + g + 8;
        if (row_a < N_ENTC) {
            float* pr = g_P + ((size_t)b * N_ENTC + row_a) * N_ENTC;
            if (col < N_ENTC)     pr[col]     = acc[nt][0] * SQRT_H;
            if (col + 1 < N_ENTC) pr[col + 1] = acc[nt][1] * SQRT_H;
        }
        if (row_b < N_ENTC) {
            float* pr = g_P + ((size_t)b * N_ENTC + row_b) * N_ENTC;
            if (col < N_ENTC)     pr[col]     = acc[nt][2] * SQRT_H;
            if (col + 1 < N_ENTC) pr[col + 1] = acc[nt][3] * SQRT_H;
        }
    }
}

// QKV projection via TC
__global__ void __launch_bounds__(256) k_qkv_tc() {
    __shared__ __align__(16) float sQ[2][128 * 20];
    __shared__ __align__(16) uint32_t Kh[2][64 * 20], Kl[2][64 * 20];
    int which = blockIdx.x >> 1;
    int c0 = (blockIdx.x & 1) * 64;
    int r0 = blockIdx.y * 128;
    int tid = threadIdx.x;
    int warp = tid >> 5, lane = tid & 31;
    int g = lane >> 2, tig = lane & 3;
    int mr = warp * 16;
    const float* Wt = g_Wt + which * H_DIM * H_DIM;
    int qrow0 = tid >> 2, seg = tid & 3;
    int a0off = (r0 + qrow0) * H_DIM + seg * 4;
    int a1off = (r0 + qrow0 + 64) * H_DIM + seg * 4;
    int boff  = (c0 + qrow0) * H_DIM + seg * 4;
    float acc[8][4];
    #pragma unroll
    for (int nt = 0; nt < 8; nt++)
        #pragma unroll
        for (int j = 0; j < 4; j++) acc[nt][j] = 0.f;
    tc_gemm_core(g_X, Wt, true, true, true, a0off, a1off, boff, acc,
                 sQ[0], sQ[1], Kh[0], Kl[0], Kh[1], Kl[1]);
    float* outp = (which == 0) ? g_Q : (which == 1) ? g_Kt : g_V;
    #pragma unroll
    for (int nt = 0; nt < 8; nt++) {
        int col = c0 + nt * 8 + 2 * tig;
        float b0 = g_Wb[which * H_DIM + col];
        float b1 = g_Wb[which * H_DIM + col + 1];
        int row_a = r0 + mr + g, row_b = r0 + mr + g + 8;
        outp[(size_t)row_a * H_DIM + col]     = acc[nt][0] + b0;
        outp[(size_t)row_a * H_DIM + col + 1] = acc[nt][1] + b1;
        outp[(size_t)row_b * H_DIM + col]     = acc[nt][2] + b0;
        outp[(size_t)row_b * H_DIM + col + 1] = acc[nt][3] + b1;
    }
}

// row softmax: single expf pass
__global__ void k_rowsm() {
    __shared__ __align__(16) float srow[N_ENTC];
    __shared__ float shm[8];
    __shared__ float s_mx, s_sum;
    size_t bn = blockIdx.x;
    float* row = g_P + bn * N_ENTC;
    int tid = threadIdx.x;  // 256 thr
    for (int i = tid; i < N_ENTC / 4; i += 256)
        ((float4*)srow)[i] = ((const float4*)row)[i];
    __syncthreads();
    float mx = -INFINITY;
    for (int m = tid; m < N_ENTC; m += 256) mx = fmaxf(mx, srow[m]);
    #pragma unroll
    for (int o = 16; o; o >>= 1) mx = fmaxf(mx, __shfl_xor_sync(0xffffffffu, mx, o));
    if ((tid & 31) == 0) shm[tid >> 5] = mx;
    __syncthreads();
    if (tid == 0) { float v = shm[0]; for (int w = 1; w < 8; w++) v = fmaxf(v, shm[w]); s_mx = v; }
    __syncthreads();
    float M = s_mx, sum = 0.f;
    for (int m = tid; m < N_ENTC; m += 256) {
        float t = expf(srow[m] - M);
        srow[m] = t;
        sum += t;
    }
    #pragma unroll
    for (int o = 16; o; o >>= 1) sum += __shfl_xor_sync(0xffffffffu, sum, o);
    if ((tid & 31) == 0) shm[tid >> 5] = sum;
    __syncthreads();
    if (tid == 0) { float v = 0.f; for (int w = 0; w < 8; w++) v += shm[w]; s_sum = v; }
    __syncthreads();
    float inv = 1.f / s_sum;
    for (int m = tid; m < N_ENTC; m += 256) row[m] = srow[m] * inv;
}

// importance stage 1: partial double sums over 8 n-chunks (deterministic).
__global__ void k_imp_part() {
    int m = blockIdx.x * 256 + threadIdx.x;
    int nc = blockIdx.y, b = blockIdx.z;
    if (m >= N_ENTC) return;
    const float* base = g_P + (size_t)b * N_ENTC * N_ENTC + m;
    int n0 = nc * NC_LEN, n1 = n0 + NC_LEN;
    double a0 = 0.0, a1 = 0.0, a2 = 0.0, a3 = 0.0;
    int n = n0;
    for (; n + 4 <= n1; n += 4) {
        a0 += (double)base[(size_t)(n+0) * N_ENTC];
        a1 += (double)base[(size_t)(n+1) * N_ENTC];
        a2 += (double)base[(size_t)(n+2) * N_ENTC];
        a3 += (double)base[(size_t)(n+3) * N_ENTC];
    }
    for (; n < n1; n++) a0 += (double)base[(size_t)n * N_ENTC];
    g_imp_part[((size_t)b * NCHUNK + nc) * N_ENTC + m] = (a0 + a1) + (a2 + a3);
}

// importance stage 2 + top-K rank
__global__ void k_topk() {
    __shared__ float sv[N_ENTC];
    int b = blockIdx.y, tid = threadIdx.x;  // 256 thr
    const double* pp = g_imp_part + (size_t)b * NCHUNK * N_ENTC;
    for (int m = tid; m < N_ENTC; m += 256) {
        double s = 0.0;
        #pragma unroll
        for (int c = 0; c < NCHUNK; c++) s += pp[(size_t)c * N_ENTC + m];
        sv[m] = (float)(s * (1.0 / (double)N_ENTC));
    }
    __syncthreads();
    int m = blockIdx.x * 256 + tid;
    if (m >= N_ENTC) return;
    float vm = sv[m];
    int rank = 0;
    for (int n = 0; n < N_ENTC; n++) {
        float vn = sv[n];
        rank += (vn > vm) ? 1 : 0;
        rank += (vn == vm && n < m) ? 1 : 0;
    }
    if (rank < KSEL) g_idx[b * KSEL + rank] = m;
}

// attended rows for selected indices
__global__ void k_attend_sel() {
    __shared__ __align__(16) float sP[32][68];
    __shared__ __align__(16) float sV[32][132];
    __shared__ int s_idx[64];
    int b = blockIdx.y;
    int r0 = blockIdx.x * 64;
    int tid = threadIdx.x, tx = tid & 15, ty = tid >> 4;  // 256 thr
    if (tid < 64) {
        int sr = r0 + tid;
        s_idx[tid] = (sr < KSEL) ? g_idx[b * KSEL + sr] : 0;
    }
    __syncthreads();
    const float* Pb = g_P + (size_t)b * N_ENTC * N_ENTC;
    const float* Vb = g_V + (size_t)b * N_ENTC * H_DIM;
    float acc[2][4][4];
    #pragma unroll
    for (int h = 0; h < 2; h++)
        #pragma unroll
        for (int i = 0; i < 4; i++)
            #pragma unroll
            for (int j = 0; j < 4; j++) acc[h][i][j] = 0.f;
    for (int k0 = 0; k0 < N_ENTC; k0 += 32) {
        #pragma unroll
        for (int p = 0; p < 8; p++) {
            int lin = tid + 256 * p;
            int kk = lin & 31, row = lin >> 5;
            int gk = k0 + kk;
            bool rv = (r0 + row) < KSEL;
            sP[kk][row] = (rv && gk < N_ENTC) ? Pb[(size_t)s_idx[row] * N_ENTC + gk] : 0.f;
        }
        #pragma unroll
        for (int p = 0; p < 16; p++) {
            int lin = tid + 256 * p;
            int col = lin & 127, kk2 = lin >> 7;
            int gk2 = k0 + kk2;
            sV[kk2][col] = (gk2 < N_ENTC) ? Vb[(size_t)gk2 * H_DIM + col] : 0.f;
        }
        __syncthreads();
        #pragma unroll
        for (int kk = 0; kk < 32; kk++) {
            float4 a = *(const float4*)&sP[kk][ty * 4];
            float ar[4] = {a.x, a.y, a.z, a.w};
            #pragma unroll
            for (int h = 0; h < 2; h++) {
                float4 bb = *(const float4*)&sV[kk][h * 64 + tx * 4];
                float br[4] = {bb.x, bb.y, bb.z, bb.w};
                #pragma unroll
                for (int i = 0; i < 4; i++)
                    #pragma unroll
                    for (int j = 0; j < 4; j++) acc[h][i][j] += ar[i] * br[j];
            }
        }
        __syncthreads();
    }
    #pragma unroll
    for (int h = 0; h < 2; h++)
        #pragma unroll
        for (int i = 0; i < 4; i++) {
            int gr = r0 + ty * 4 + i;
            if (gr >= KSEL) continue;
            #pragma unroll
            for (int j = 0; j < 4; j++) {
                int gc = h * 64 + tx * 4 + j;
                g_attend[((size_t)b * KSEL + gr) * H_DIM + gc] = acc[h][i][j];
            }
        }
}

// out[b,k,:] = tanh(attend_compact[b,k,:] @ W_kg + b_kg)
__global__ void k_sel(const float* __restrict__ W_kg, const float* __restrict__ b_kg,
                      float* __restrict__ out) {
    __shared__ float sx[16][H_DIM];
    int tid = threadIdx.x;  // 128 thr
    int b = blockIdx.y;
    int kt = blockIdx.x * 16;
    int nvalid = min(16, KSEL - kt);
    for (int r = 0; r < nvalid; r++)
        sx[r][tid] = g_attend[((size_t)b * KSEL + kt + r) * H_DIM + tid];
    __syncthreads();
    float acc[16];
    #pragma unroll
    for (int r = 0; r < 16; r++) acc[r] = 0.f;
    #pragma unroll 2
    for (int d = 0; d < H_DIM; d++) {
        float w = W_kg[d * H_DIM + tid];
        #pragma unroll
        for (int r = 0; r < 16; r++) acc[r] += sx[r][d] * w;
    }
    float bb = b_kg[tid];
    for (int r = 0; r < nvalid; r++)
        out[((size_t)b * KSEL + kt + r) * H_DIM + tid] = tanhf(acc[r] + bb);
}

extern "C" void kernel_launch(void* const* d_in, const int* in_sizes, int n_in,
                              void* d_out, int out_size) {
    const float *ent_emb, *rel_emb, *rel_mask, *qe;
    const float *W_tok, *b_tok, *W_key, *b_key, *W_comp, *b_comp;
    const float *Wq, *bq, *Wk, *bk, *Wv, *bv, *W_kg, *b_kg;
    const int *src, *dst, *rel_id;
    if (in_sizes[5] == E_EDG) {
        ent_emb = (const float*)d_in[0];  rel_emb = (const float*)d_in[1];
        rel_mask = (const float*)d_in[3]; qe = (const float*)d_in[4];
        src = (const int*)d_in[5]; dst = (const int*)d_in[6]; rel_id = (const int*)d_in[7];
        W_tok = (const float*)d_in[8];  b_tok = (const float*)d_in[9];
        W_key = (const float*)d_in[10]; b_key = (const float*)d_in[11];
        W_comp = (const float*)d_in[12]; b_comp = (const float*)d_in[13];
        Wq = (const float*)d_in[14]; bq = (const float*)d_in[15];
        Wk = (const float*)d_in[16]; bk = (const float*)d_in[17];
        Wv = (const float*)d_in[18]; bv = (const float*)d_in[19];
        W_kg = (const float*)d_in[20]; b_kg = (const float*)d_in[21];
    } else {
        ent_emb = (const float*)d_in[0];  rel_emb = (const float*)d_in[1];
        rel_mask = (const float*)d_in[3]; qe = (const float*)d_in[4];
        W_tok = (const float*)d_in[5];  b_tok = (const float*)d_in[6];
        W_key = (const float*)d_in[7];  b_key = (const float*)d_in[8];
        W_comp = (const float*)d_in[9]; b_comp = (const float*)d_in[10];
        Wq = (const float*)d_in[11]; bq = (const float*)d_in[12];
        Wk = (const float*)d_in[13]; bk = (const float*)d_in[14];
        Wv = (const float*)d_in[15]; bv = (const float*)d_in[16];
        W_kg = (const float*)d_in[17]; b_kg = (const float*)d_in[18];
        src = (const int*)d_in[19]; dst = (const int*)d_in[20]; rel_id = (const int*)d_in[21];
    }
    float* out = (float*)d_out;

    k_zero<<<(B_DIM * N_ENTC * H_DIM + 255) / 256, 256>>>(Wq, bq, Wk, bk, Wv, bv);
    k_qbar<<<B_DIM, 128>>>(qe, W_tok, b_tok);
    k_edge<<<E_EDG / 16, 128>>>(ent_emb, rel_emb, rel_mask, src, dst, rel_id,
                                 W_key, b_key, W_comp, b_comp);
    k_w<<<E_EDG / 8, 256>>>();
    k_attsm<<<B_DIM, 1024>>>();
    k_m1<<<(B_DIM * E_EDG + 255) / 256, 256>>>(src);
    k_m2<<<(B_DIM * E_EDG + 255) / 256, 256>>>(src);
    k_msg<<<E_EDG, 128>>>(src, dst);
    k_ln<<<NROWS / 16, 128>>>();
    {
        dim3 g(6, NROWS / 128);
        k_qkv_tc<<<g, 256>>>();
    }
    {
        dim3 g((N_ENTC + 63) / 64, (N_ENTC + 127) / 128, B_DIM);
        k_scores_tc<<<g, 256>>>();
    }
    k_rowsm<<<B_DIM * N_ENTC, 256>>>();
    {
        dim3 g((N_ENTC + 255) / 256, NCHUNK, B_DIM);
        k_imp_part<<<g, 256>>>();
    }
    {
        dim3 g((N_ENTC + 255) / 256, B_DIM);
        k_topk<<<g, 256>>>();
    }
    {
        dim3 g((KSEL + 63) / 64, B_DIM);
        k_attend_sel<<<g, 256>>>();
    }
    {
        dim3 g((KSEL + 15) / 16, B_DIM);
        k_sel<<<g, 128>>>(W_kg, b_kg, out);
    }
}

// round 15
// speedup vs baseline: 1.0589x; 1.0137x over previous
#include <cuda_runtime.h>
#include <math.h>
#include <stdint.h>

#define N_ENTC 1968
#define E_EDG  20000
#define S_DIM  16
#define D2H    256
#define H_DIM  128
#define B_DIM  8
#define T_DIM  20
#define KSEL   196
#define NCHUNK 8
#define NC_LEN 246
#define NROWS  (B_DIM * N_ENTC)
#define UPITCH 260
#define SQRT_H 11.313708498984761f

__device__ float    g_qbar[B_DIM * H_DIM];
__device__ float    g_kbar[(size_t)E_EDG * H_DIM];
__device__ float    g_cf[(size_t)E_EDG * H_DIM];
__device__ float    g_w[(size_t)B_DIM * E_EDG];
__device__ float    g_att[(size_t)B_DIM * E_EDG];
__device__ unsigned g_m1[B_DIM * N_ENTC];
__device__ unsigned g_m2[B_DIM * N_ENTC];
__device__ float    g_neigh[(size_t)B_DIM * N_ENTC * H_DIM];
__device__ float    g_X[(size_t)NROWS * H_DIM];
__device__ float    g_Wt[3 * H_DIM * H_DIM];
__device__ float    g_Wb[3 * H_DIM];
__device__ float    g_Q[(size_t)B_DIM * N_ENTC * H_DIM];
__device__ float    g_Kt[(size_t)B_DIM * N_ENTC * H_DIM];
__device__ float    g_V[(size_t)B_DIM * N_ENTC * H_DIM];
__device__ float    g_P[(size_t)B_DIM * N_ENTC * N_ENTC];
__device__ float    g_attend[(size_t)B_DIM * KSEL * H_DIM];
__device__ double   g_imp_part[(size_t)B_DIM * NCHUNK * N_ENTC];
__device__ int      g_idx[B_DIM * KSEL];

// fused: zero neigh/m1/m2 + transpose QKV weights + stage biases
__global__ void k_zero(const float* __restrict__ Wq, const float* __restrict__ bq,
                       const float* __restrict__ Wk, const float* __restrict__ bk,
                       const float* __restrict__ Wv, const float* __restrict__ bv) {
    int i = blockIdx.x * 256 + threadIdx.x;
    if (i < B_DIM * N_ENTC * H_DIM) g_neigh[i] = 0.f;
    if (i < B_DIM * N_ENTC) { g_m1[i] = 0u; g_m2[i] = 0u; }
    if (i < 3 * H_DIM * H_DIM) {
        int which = i >> 14, r = i & 16383;
        int c = r >> 7, k = r & 127;
        const float* W = (which == 0) ? Wq : (which == 1) ? Wk : Wv;
        g_Wt[i] = W[k * H_DIM + c];
    }
    if (i < 3 * H_DIM) {
        int which = i >> 7, c = i & 127;
        const float* bb = (which == 0) ? bq : (which == 1) ? bk : bv;
        g_Wb[i] = bb[c];
    }
}

// qbar[b] = (mean_t question[b]) @ W_tok + b_tok
__global__ void k_qbar(const float* __restrict__ qe, const float* __restrict__ W_tok,
                       const float* __restrict__ b_tok) {
    __shared__ float qs[D2H];
    int b = blockIdx.x, tid = threadIdx.x;  // 128 thr
    #pragma unroll
    for (int k = 0; k < 2; k++) {
        int d = tid + 128 * k;
        float s = 0.f;
        #pragma unroll
        for (int t = 0; t < T_DIM; t++) s += qe[((size_t)b * T_DIM + t) * D2H + d];
        qs[d] = s * (1.f / (float)T_DIM);
    }
    __syncthreads();
    float acc = b_tok[tid];
    #pragma unroll 4
    for (int d = 0; d < D2H; d++) acc += qs[d] * W_tok[d * H_DIM + tid];
    g_qbar[b * H_DIM + tid] = acc;
}

// per-edge kernel: u/v staged [e][d]; FMA sequence bit-identical to prior rounds.
__global__ void k_edge(const float* __restrict__ ent_emb, const float* __restrict__ rel_emb,
                       const float* __restrict__ rel_mask, const int* __restrict__ src,
                       const int* __restrict__ dst, const int* __restrict__ rel_id,
                       const float* __restrict__ W_key, const float* __restrict__ b_key,
                       const float* __restrict__ W_comp, const float* __restrict__ b_comp) {
    __shared__ __align__(16) float s_u[16 * UPITCH];
    __shared__ __align__(16) float s_v[16 * UPITCH];
    __shared__ float s_mask[16][S_DIM];
    __shared__ float s_eps[16], s_msum[16];
    __shared__ int   s_src[16], s_dst[16], s_rid[16];
    __shared__ float s_wc[S_DIM];
    int tid = threadIdx.x;  // 128 thr
    int e0  = blockIdx.x * 16;
    if (tid < 16) { s_src[tid] = src[e0+tid]; s_dst[tid] = dst[e0+tid]; s_rid[tid] = rel_id[e0+tid]; }
    if (tid >= 32 && tid < 32 + S_DIM) s_wc[tid - 32] = W_comp[tid - 32];
    __syncthreads();
    for (int i = tid; i < 16 * S_DIM; i += 128) {
        int e = i / S_DIM, s = i % S_DIM;
        s_mask[e][s] = rel_mask[s_rid[e] * S_DIM + s];
    }
    __syncthreads();
    if (tid < 16) {
        float cnt = 0.f, ms = 0.f;
        #pragma unroll
        for (int s = 0; s < S_DIM; s++) { float m = s_mask[tid][s]; ms += m; cnt += (m != 0.f) ? 1.f : 0.f; }
        s_eps[tid]  = (cnt == 0.f) ? 1.f : cnt;
        s_msum[tid] = ms;
    }
    __syncthreads();
    #pragma unroll 1
    for (int it = 0; it < 8; it++) {
        int e = it * 2 + (tid >> 6);
        int f = tid & 63;
        const float4* ps = (const float4*)(ent_emb + (size_t)s_src[e] * (S_DIM * D2H));
        const float4* pd = (const float4*)(ent_emb + (size_t)s_dst[e] * (S_DIM * D2H));
        const float4* pr = (const float4*)(rel_emb + (size_t)s_rid[e] * (S_DIM * D2H));
        float4 au = make_float4(0.f, 0.f, 0.f, 0.f);
        float4 av = make_float4(0.f, 0.f, 0.f, 0.f);
        #pragma unroll
        for (int s = 0; s < S_DIM; s++) {
            float4 a = ps[s * 64 + f], r = pr[s * 64 + f], dd = pd[s * 64 + f];
            float cx = (a.x + r.x) - dd.x;
            float cy = (a.y + r.y) - dd.y;
            float cz = (a.z + r.z) - dd.z;
            float cw = (a.w + r.w) - dd.w;
            float m = s_mask[e][s], wv = s_wc[s];
            au.x += m * cx; au.y += m * cy; au.z += m * cz; au.w += m * cw;
            av.x += wv * cx; av.y += wv * cy; av.z += wv * cz; av.w += wv * cw;
        }
        *(float4*)(s_u + e * UPITCH + 4 * f) = au;
        *(float4*)(s_v + e * UPITCH + 4 * f) = av;
    }
    __syncthreads();
    float wcsum = 0.f;
    #pragma unroll
    for (int s = 0; s < S_DIM; s++) wcsum += s_wc[s];
    float ak[16], ac[16];
    #pragma unroll
    for (int e = 0; e < 16; e++) { ak[e] = 0.f; ac[e] = 0.f; }
    #pragma unroll 2
    for (int dc = 0; dc < D2H; dc += 4) {
        float w0 = W_key[(dc + 0) * H_DIM + tid];
        float w1 = W_key[(dc + 1) * H_DIM + tid];
        float w2 = W_key[(dc + 2) * H_DIM + tid];
        float w3 = W_key[(dc + 3) * H_DIM + tid];
        #pragma unroll
        for (int e = 0; e < 16; e++) {
            float4 uu = *(const float4*)(s_u + e * UPITCH + dc);
            ak[e] += uu.x * w0; ak[e] += uu.y * w1; ak[e] += uu.z * w2; ak[e] += uu.w * w3;
            float4 vv = *(const float4*)(s_v + e * UPITCH + dc);
            ac[e] += vv.x * w0; ac[e] += vv.y * w1; ac[e] += vv.z * w2; ac[e] += vv.w * w3;
        }
    }
    float bk = b_key[tid], bc = b_comp[0];
    #pragma unroll
    for (int e = 0; e < 16; e++) {
        g_kbar[(size_t)(e0+e) * H_DIM + tid] = (ak[e] + s_msum[e] * bk) / s_eps[e];
        g_cf[(size_t)(e0+e) * H_DIM + tid]   = ac[e] + wcsum * bk + bc;
    }
}

// w[b,e] = 0.125 * qbar[b] . kbar[e]
__global__ void k_w() {
    __shared__ float sq[B_DIM * H_DIM];
    int tid = threadIdx.x;  // 256 thr
    for (int i = tid; i < B_DIM * H_DIM; i += 256) sq[i] = g_qbar[i];
    __syncthreads();
    int warp = tid >> 5, lane = tid & 31;
    int e = blockIdx.x * 8 + warp;
    const float* kb = g_kbar + (size_t)e * H_DIM;
    float k0 = kb[lane], k1 = kb[lane+32], k2 = kb[lane+64], k3 = kb[lane+96];
    #pragma unroll
    for (int b = 0; b < B_DIM; b++) {
        const float* q = sq + b * H_DIM;
        float p = q[lane]*k0 + q[lane+32]*k1 + q[lane+64]*k2 + q[lane+96]*k3;
        #pragma unroll
        for (int o = 16; o; o >>= 1) p += __shfl_xor_sync(0xffffffffu, p, o);
        if (lane == 0) g_w[(size_t)b * E_EDG + e] = 0.125f * p;
    }
}

__global__ void k_attsm() {
    int b = blockIdx.x, tid = threadIdx.x;  // 1024 thr
    __shared__ float shm[32];
    __shared__ float s_mx, s_sum;
    const float* wr = g_w + (size_t)b * E_EDG;
    float mx = -INFINITY;
    for (int e = tid; e < E_EDG; e += 1024) mx = fmaxf(mx, wr[e]);
    #pragma unroll
    for (int o = 16; o; o >>= 1) mx = fmaxf(mx, __shfl_xor_sync(0xffffffffu, mx, o));
    if ((tid & 31) == 0) shm[tid >> 5] = mx;
    __syncthreads();
    if (tid == 0) { float v = shm[0]; for (int w = 1; w < 32; w++) v = fmaxf(v, shm[w]); s_mx = v; }
    __syncthreads();
    float M = s_mx, sum = 0.f;
    for (int e = tid; e < E_EDG; e += 1024) sum += expf(wr[e] - M);
    #pragma unroll
    for (int o = 16; o; o >>= 1) sum += __shfl_xor_sync(0xffffffffu, sum, o);
    if ((tid & 31) == 0) shm[tid >> 5] = sum;
    __syncthreads();
    if (tid == 0) { float v = 0.f; for (int w = 0; w < 32; w++) v += shm[w]; s_sum = v; }
    __syncthreads();
    float inv = 1.f / s_sum;
    for (int e = tid; e < E_EDG; e += 1024) g_att[(size_t)b * E_EDG + e] = expf(wr[e] - M) * inv;
}

__global__ void k_m1(const int* __restrict__ src) {
    int i = blockIdx.x * 256 + threadIdx.x;
    if (i >= B_DIM * E_EDG) return;
    int b = i / E_EDG, e = i % E_EDG;
    atomicMax(&g_m1[b * N_ENTC + src[e]], __float_as_uint(g_att[i]));
}
__global__ void k_m2(const int* __restrict__ src) {
    int i = blockIdx.x * 256 + threadIdx.x;
    if (i >= B_DIM * E_EDG) return;
    int b = i / E_EDG, e = i % E_EDG;
    unsigned v = __float_as_uint(g_att[i]);
    if (v != g_m1[b * N_ENTC + src[e]]) atomicMax(&g_m2[b * N_ENTC + src[e]], v);
}

__global__ void k_msg(const int* __restrict__ src, const int* __restrict__ dst) {
    int e = blockIdx.x, h = threadIdx.x;  // 128 thr
    float cf = g_cf[(size_t)e * H_DIM + h];
    int sn = src[e], dn = dst[e];
    #pragma unroll
    for (int b = 0; b < B_DIM; b++) {
        float a  = g_att[(size_t)b * E_EDG + e];
        float m2 = __uint_as_float(g_m2[b * N_ENTC + sn]);
        if (a >= m2) atomicAdd(&g_neigh[((size_t)b * N_ENTC + dn) * H_DIM + h], cf * a);
    }
}

// LayerNorm (bit-identical), writes g_X
__global__ void k_ln() {
    __shared__ float sx[16][H_DIM];
    int tid = threadIdx.x;  // 128 thr
    size_t r0 = (size_t)blockIdx.x * 16;
    for (int i = tid; i < 16 * H_DIM; i += 128) ((float*)sx)[i] = g_neigh[r0 * H_DIM + i];
    __syncthreads();
    int warp = tid >> 5, lane = tid & 31;
    #pragma unroll
    for (int j = 0; j < 4; j++) {
        int r = warp * 4 + j;
        float x0 = sx[r][lane], x1 = sx[r][lane+32], x2 = sx[r][lane+64], x3 = sx[r][lane+96];
        float s = x0 + x1 + x2 + x3;
        #pragma unroll
        for (int o = 16; o; o >>= 1) s += __shfl_xor_sync(0xffffffffu, s, o);
        float mu = s * (1.f / 128.f);
        float d0 = x0-mu, d1 = x1-mu, d2 = x2-mu, d3 = x3-mu;
        float q = d0*d0 + d1*d1 + d2*d2 + d3*d3;
        #pragma unroll
        for (int o = 16; o; o >>= 1) q += __shfl_xor_sync(0xffffffffu, q, o);
        float rs = rsqrtf(q * (1.f / 128.f) + 1e-5f);
        sx[r][lane] = d0*rs; sx[r][lane+32] = d1*rs; sx[r][lane+64] = d2*rs; sx[r][lane+96] = d3*rs;
    }
    __syncthreads();
    for (int i = tid; i < 16 * H_DIM; i += 128) g_X[r0 * H_DIM + i] = ((float*)sx)[i];
}

// ---------------- shared TF32 machinery ----------------
#define MMA_TF32(c, a0, a1, a2, a3, b0, b1)                                   \
    asm volatile(                                                             \
        "mma.sync.aligned.m16n8k8.row.col.f32.tf32.tf32.f32 "                 \
        "{%0,%1,%2,%3}, {%4,%5,%6,%7}, {%8,%9}, {%0,%1,%2,%3};"               \
        : "+f"(c[0]), "+f"(c[1]), "+f"(c[2]), "+f"(c[3])                      \
        : "r"(a0), "r"(a1), "r"(a2), "r"(a3), "r"(b0), "r"(b1))

__device__ __forceinline__ void tf32_split(float x, uint32_t& h, uint32_t& l) {
    asm("cvt.rna.tf32.f32 %0, %1;" : "=r"(h) : "f"(x));
    float r = x - __uint_as_float(h);
    asm("cvt.rna.tf32.f32 %0, %1;" : "=r"(l) : "f"(r));
}

__device__ __forceinline__ void cp16(uint32_t dst, const void* src, bool valid) {
    int sz = valid ? 16 : 0;
    asm volatile("cp.async.cg.shared.global [%0], [%1], 16, %2;"
                 :: "r"(dst), "l"(src), "r"(sz));
}
#define CP_COMMIT() asm volatile("cp.async.commit_group;")
#define CP_WAIT1()  asm volatile("cp.async.wait_group 1;" ::: "memory")
#define CP_WAIT0()  asm volatile("cp.async.wait_group 0;" ::: "memory")
#define PHI(kk) (((kk) & 8) | (((kk) & 3) << 1) | (((kk) >> 2) & 1))

__device__ __forceinline__ void tc_gemm_core(
    const float* __restrict__ Arows, const float* __restrict__ Brows,
    bool av0, bool av1, bool bv,
    int arow0_off, int arow1_off, int brow_off,
    float (&acc)[8][4],
    float* sQ0, float* sQ1,
    uint32_t* Kh0, uint32_t* Kl0, uint32_t* Kh1, uint32_t* Kl1)
{
    int tid = threadIdx.x;
    int warp = tid >> 5, lane = tid & 31;
    int g = lane >> 2, tig = lane & 3;
    int mr = warp * 16;
    int qrow0 = tid >> 2, seg = tid & 3;
    float* sQb[2]  = { sQ0, sQ1 };
    uint32_t* Khb[2] = { Kh0, Kh1 };
    uint32_t* Klb[2] = { Kl0, Kl1 };
    uint32_t qd0[2], qd1[2];
    #pragma unroll
    for (int bf = 0; bf < 2; bf++) {
        qd0[bf] = (uint32_t)__cvta_generic_to_shared(&sQb[bf][qrow0 * 20 + seg * 4]);
        qd1[bf] = (uint32_t)__cvta_generic_to_shared(&sQb[bf][(qrow0 + 64) * 20 + seg * 4]);
    }
    const float* qsrc0 = Arows + arow0_off;
    const float* qsrc1 = Arows + arow1_off;
    const float* ksrc  = Brows + brow_off;

    cp16(qd0[0], qsrc0, av0);
    cp16(qd1[0], qsrc1, av1);
    CP_COMMIT();
    {
        float4 kr = bv ? *(const float4*)ksrc : make_float4(0.f,0.f,0.f,0.f);
        float kvv[4] = {kr.x, kr.y, kr.z, kr.w};
        int row = tid >> 2;
        #pragma unroll
        for (int i = 0; i < 4; i++) {
            uint32_t h, l; tf32_split(kvv[i], h, l);
            int kk = seg * 4 + i;
            Khb[0][row * 20 + PHI(kk)] = h;
            Klb[0][row * 20 + PHI(kk)] = l;
        }
    }

    #pragma unroll 1
    for (int c = 0; c < 8; c++) {
        int buf = c & 1;
        float4 kr;
        if (c < 7) {
            int kc = (c + 1) * 16;
            cp16(qd0[buf ^ 1], qsrc0 + kc, av0);
            cp16(qd1[buf ^ 1], qsrc1 + kc, av1);
            CP_COMMIT();
            kr = bv ? *(const float4*)(ksrc + kc) : make_float4(0.f,0.f,0.f,0.f);
            CP_WAIT1();
        } else {
            CP_WAIT0();
        }
        __syncthreads();
        const float* Qs = sQb[buf];
        const uint32_t* KH = Khb[buf];
        const uint32_t* KL = Klb[buf];
        #pragma unroll
        for (int ks = 0; ks < 2; ks++) {
            int kb = ks * 8;
            float fa0 = Qs[(mr + g)     * 20 + kb + tig];
            float fa1 = Qs[(mr + g + 8) * 20 + kb + tig];
            float fa2 = Qs[(mr + g)     * 20 + kb + tig + 4];
            float fa3 = Qs[(mr + g + 8) * 20 + kb + tig + 4];
            uint32_t ah0, al0, ah1, al1, ah2, al2, ah3, al3;
            tf32_split(fa0, ah0, al0); tf32_split(fa1, ah1, al1);
            tf32_split(fa2, ah2, al2); tf32_split(fa3, ah3, al3);
            #pragma unroll
            for (int nt = 0; nt < 8; nt++) {
                uint2 bh = *(const uint2*)&KH[(nt * 8 + g) * 20 + kb + 2 * tig];
                uint2 bl = *(const uint2*)&KL[(nt * 8 + g) * 20 + kb + 2 * tig];
                MMA_TF32(acc[nt], al0, al1, al2, al3, bh.x, bh.y);
                MMA_TF32(acc[nt], ah0, ah1, ah2, ah3, bl.x, bl.y);
                MMA_TF32(acc[nt], ah0, ah1, ah2, ah3, bh.x, bh.y);
            }
        }
        if (c < 7) {
            int nb = buf ^ 1;
            float kvv[4] = {kr.x, kr.y, kr.z, kr.w};
            int row = tid >> 2;
            #pragma unroll
            for (int i = 0; i < 4; i++) {
                uint32_t h, l; tf32_split(kvv[i], h, l);
                int kk = seg * 4 + i;
                Khb[nb][row * 20 + PHI(kk)] = h;
                Klb[nb][row * 20 + PHI(kk)] = l;
            }
        }
        __syncthreads();
    }
}

// scores: P = sqrt(H) * Q @ K^T
__global__ void __launch_bounds__(256) k_scores_tc() {
    __shared__ __align__(16) float sQ[2][128 * 20];
    __shared__ __align__(16) uint32_t Kh[2][64 * 20], Kl[2][64 * 20];
    int b = blockIdx.z;
    int r0 = blockIdx.y * 128, c0 = blockIdx.x * 64;
    int tid = threadIdx.x;
    int warp = tid >> 5, lane = tid & 31;
    int g = lane >> 2, tig = lane & 3;
    int mr = warp * 16;
    const float* Qb = g_Q  + (size_t)b * N_ENTC * H_DIM;
    const float* Kb = g_Kt + (size_t)b * N_ENTC * H_DIM;
    int qrow0 = tid >> 2, seg = tid & 3;
    bool av0 = (r0 + qrow0) < N_ENTC;
    bool av1 = (r0 + qrow0 + 64) < N_ENTC;
    bool bv  = (c0 + qrow0) < N_ENTC;
    int a0off = (av0 ? (r0 + qrow0)      : 0) * H_DIM + seg * 4;
    int a1off = (av1 ? (r0 + qrow0 + 64) : 0) * H_DIM + seg * 4;
    int boff  = (bv  ? (c0 + qrow0)      : 0) * H_DIM + seg * 4;
    float acc[8][4];
    #pragma unroll
    for (int nt = 0; nt < 8; nt++)
        #pragma unroll
        for (int j = 0; j < 4; j++) acc[nt][j] = 0.f;
    tc_gemm_core(Qb, Kb, av0, av1, bv, a0off, a1off, boff, acc,
                 sQ[0], sQ[1], Kh[0], Kl[0], Kh[1], Kl[1]);
    #pragma unroll
    for (int nt = 0; nt < 8; nt++) {
        int col = c0 + nt * 8 + 2 * tig;
        int row_a = r0 + mr + g, row_b = r0 + mr + g + 8;
        if (row_a < N_ENTC) {
            float* pr = g_P + ((size_t)b * N_ENTC + row_a) * N_ENTC;
            if (col < N_ENTC)     pr[col]     = acc[nt][0] * SQRT_H;
            if (col + 1 < N_ENTC) pr[col + 1] = acc[nt][1] * SQRT_H;
        }
        if (row_b < N_ENTC) {
            float* pr = g_P + ((size_t)b * N_ENTC + row_b) * N_ENTC;
            if (col < N_ENTC)     pr[col]     = acc[nt][2] * SQRT_H;
            if (col + 1 < N_ENTC) pr[col + 1] = acc[nt][3] * SQRT_H;
        }
    }
}

// QKV projection via TC
__global__ void __launch_bounds__(256) k_qkv_tc() {
    __shared__ __align__(16) float sQ[2][128 * 20];
    __shared__ __align__(16) uint32_t Kh[2][64 * 20], Kl[2][64 * 20];
    int which = blockIdx.x >> 1;
    int c0 = (blockIdx.x & 1) * 64;
    int r0 = blockIdx.y * 128;
    int tid = threadIdx.x;
    int warp = tid >> 5, lane = tid & 31;
    int g = lane >> 2, tig = lane & 3;
    int mr = warp * 16;
    const float* Wt = g_Wt + which * H_DIM * H_DIM;
    int qrow0 = tid >> 2, seg = tid & 3;
    int a0off = (r0 + qrow0) * H_DIM + seg * 4;
    int a1off = (r0 + qrow0 + 64) * H_DIM + seg * 4;
    int boff  = (c0 + qrow0) * H_DIM + seg * 4;
    float acc[8][4];
    #pragma unroll
    for (int nt = 0; nt < 8; nt++)
        #pragma unroll
        for (int j = 0; j < 4; j++) acc[nt][j] = 0.f;
    tc_gemm_core(g_X, Wt, true, true, true, a0off, a1off, boff, acc,
                 sQ[0], sQ[1], Kh[0], Kl[0], Kh[1], Kl[1]);
    float* outp = (which == 0) ? g_Q : (which == 1) ? g_Kt : g_V;
    #pragma unroll
    for (int nt = 0; nt < 8; nt++) {
        int col = c0 + nt * 8 + 2 * tig;
        float b0 = g_Wb[which * H_DIM + col];
        float b1 = g_Wb[which * H_DIM + col + 1];
        int row_a = r0 + mr + g, row_b = r0 + mr + g + 8;
        outp[(size_t)row_a * H_DIM + col]     = acc[nt][0] + b0;
        outp[(size_t)row_a * H_DIM + col + 1] = acc[nt][1] + b1;
        outp[(size_t)row_b * H_DIM + col]     = acc[nt][2] + b0;
        outp[(size_t)row_b * H_DIM + col + 1] = acc[nt][3] + b1;
    }
}

// row softmax: single expf pass; P loaded evict-first (streaming)
__global__ void k_rowsm() {
    __shared__ __align__(16) float srow[N_ENTC];
    __shared__ float shm[8];
    __shared__ float s_mx, s_sum;
    size_t bn = blockIdx.x;
    float* row = g_P + bn * N_ENTC;
    int tid = threadIdx.x;  // 256 thr
    for (int i = tid; i < N_ENTC / 4; i += 256)
        ((float4*)srow)[i] = __ldcs((const float4*)row + i);
    __syncthreads();
    float mx = -INFINITY;
    for (int m = tid; m < N_ENTC; m += 256) mx = fmaxf(mx, srow[m]);
    #pragma unroll
    for (int o = 16; o; o >>= 1) mx = fmaxf(mx, __shfl_xor_sync(0xffffffffu, mx, o));
    if ((tid & 31) == 0) shm[tid >> 5] = mx;
    __syncthreads();
    if (tid == 0) { float v = shm[0]; for (int w = 1; w < 8; w++) v = fmaxf(v, shm[w]); s_mx = v; }
    __syncthreads();
    float M = s_mx, sum = 0.f;
    for (int m = tid; m < N_ENTC; m += 256) {
        float t = expf(srow[m] - M);
        srow[m] = t;
        sum += t;
    }
    #pragma unroll
    for (int o = 16; o; o >>= 1) sum += __shfl_xor_sync(0xffffffffu, sum, o);
    if ((tid & 31) == 0) shm[tid >> 5] = sum;
    __syncthreads();
    if (tid == 0) { float v = 0.f; for (int w = 0; w < 8; w++) v += shm[w]; s_sum = v; }
    __syncthreads();
    float inv = 1.f / s_sum;
    for (int m = tid; m < N_ENTC; m += 256) row[m] = srow[m] * inv;
}

// importance stage 1: partial double sums; P read evict-first (streaming)
__global__ void k_imp_part() {
    int m = blockIdx.x * 256 + threadIdx.x;
    int nc = blockIdx.y, b = blockIdx.z;
    if (m >= N_ENTC) return;
    const float* base = g_P + (size_t)b * N_ENTC * N_ENTC + m;
    int n0 = nc * NC_LEN, n1 = n0 + NC_LEN;
    double a0 = 0.0, a1 = 0.0, a2 = 0.0, a3 = 0.0;
    int n = n0;
    for (; n + 4 <= n1; n += 4) {
        a0 += (double)__ldcs(base + (size_t)(n+0) * N_ENTC);
        a1 += (double)__ldcs(base + (size_t)(n+1) * N_ENTC);
        a2 += (double)__ldcs(base + (size_t)(n+2) * N_ENTC);
        a3 += (double)__ldcs(base + (size_t)(n+3) * N_ENTC);
    }
    for (; n < n1; n++) a0 += (double)__ldcs(base + (size_t)n * N_ENTC);
    g_imp_part[((size_t)b * NCHUNK + nc) * N_ENTC + m] = (a0 + a1) + (a2 + a3);
}

// importance stage 2 + top-K rank
__global__ void k_topk() {
    __shared__ float sv[N_ENTC];
    int b = blockIdx.y, tid = threadIdx.x;  // 256 thr
    const double* pp = g_imp_part + (size_t)b * NCHUNK * N_ENTC;
    for (int m = tid; m < N_ENTC; m += 256) {
        double s = 0.0;
        #pragma unroll
        for (int c = 0; c < NCHUNK; c++) s += pp[(size_t)c * N_ENTC + m];
        sv[m] = (float)(s * (1.0 / (double)N_ENTC));
    }
    __syncthreads();
    int m = blockIdx.x * 256 + tid;
    if (m >= N_ENTC) return;
    float vm = sv[m];
    int rank = 0;
    for (int n = 0; n < N_ENTC; n++) {
        float vn = sv[n];
        rank += (vn > vm) ? 1 : 0;
        rank += (vn == vm && n < m) ? 1 : 0;
    }
    if (rank < KSEL) g_idx[b * KSEL + rank] = m;
}

// attended rows for selected indices
__global__ void k_attend_sel() {
    __shared__ __align__(16) float sP[32][68];
    __shared__ __align__(16) float sV[32][132];
    __shared__ int s_idx[64];
    int b = blockIdx.y;
    int r0 = blockIdx.x * 64;
    int tid = threadIdx.x, tx = tid & 15, ty = tid >> 4;  // 256 thr
    if (tid < 64) {
        int sr = r0 + tid;
        s_idx[tid] = (sr < KSEL) ? g_idx[b * KSEL + sr] : 0;
    }
    __syncthreads();
    const float* Pb = g_P + (size_t)b * N_ENTC * N_ENTC;
    const float* Vb = g_V + (size_t)b * N_ENTC * H_DIM;
    float acc[2][4][4];
    #pragma unroll
    for (int h = 0; h < 2; h++)
        #pragma unroll
        for (int i = 0; i < 4; i++)
            #pragma unroll
            for (int j = 0; j < 4; j++) acc[h][i][j] = 0.f;
    for (int k0 = 0; k0 < N_ENTC; k0 += 32) {
        #pragma unroll
        for (int p = 0; p < 8; p++) {
            int lin = tid + 256 * p;
            int kk = lin & 31, row = lin >> 5;
            int gk = k0 + kk;
            bool rv = (r0 + row) < KSEL;
            sP[kk][row] = (rv && gk < N_ENTC) ? Pb[(size_t)s_idx[row] * N_ENTC + gk] : 0.f;
        }
        #pragma unroll
        for (int p = 0; p < 16; p++) {
            int lin = tid + 256 * p;
            int col = lin & 127, kk2 = lin >> 7;
            int gk2 = k0 + kk2;
            sV[kk2][col] = (gk2 < N_ENTC) ? Vb[(size_t)gk2 * H_DIM + col] : 0.f;
        }
        __syncthreads();
        #pragma unroll
        for (int kk = 0; kk < 32; kk++) {
            float4 a = *(const float4*)&sP[kk][ty * 4];
            float ar[4] = {a.x, a.y, a.z, a.w};
            #pragma unroll
            for (int h = 0; h < 2; h++) {
                float4 bb = *(const float4*)&sV[kk][h * 64 + tx * 4];
                float br[4] = {bb.x, bb.y, bb.z, bb.w};
                #pragma unroll
                for (int i = 0; i < 4; i++)
                    #pragma unroll
                    for (int j = 0; j < 4; j++) acc[h][i][j] += ar[i] * br[j];
            }
        }
        __syncthreads();
    }
    #pragma unroll
    for (int h = 0; h < 2; h++)
        #pragma unroll
        for (int i = 0; i < 4; i++) {
            int gr = r0 + ty * 4 + i;
            if (gr >= KSEL) continue;
            #pragma unroll
            for (int j = 0; j < 4; j++) {
                int gc = h * 64 + tx * 4 + j;
                g_attend[((size_t)b * KSEL + gr) * H_DIM + gc] = acc[h][i][j];
            }
        }
}

// out[b,k,:] = tanh(attend_compact[b,k,:] @ W_kg + b_kg)
__global__ void k_sel(const float* __restrict__ W_kg, const float* __restrict__ b_kg,
                      float* __restrict__ out) {
    __shared__ float sx[16][H_DIM];
    int tid = threadIdx.x;  // 128 thr
    int b = blockIdx.y;
    int kt = blockIdx.x * 16;
    int nvalid = min(16, KSEL - kt);
    for (int r = 0; r < nvalid; r++)
        sx[r][tid] = g_attend[((size_t)b * KSEL + kt + r) * H_DIM + tid];
    __syncthreads();
    float acc[16];
    #pragma unroll
    for (int r = 0; r < 16; r++) acc[r] = 0.f;
    #pragma unroll 2
    for (int d = 0; d < H_DIM; d++) {
        float w = W_kg[d * H_DIM + tid];
        #pragma unroll
        for (int r = 0; r < 16; r++) acc[r] += sx[r][d] * w;
    }
    float bb = b_kg[tid];
    for (int r = 0; r < nvalid; r++)
        out[((size_t)b * KSEL + kt + r) * H_DIM + tid] = tanhf(acc[r] + bb);
}

extern "C" void kernel_launch(void* const* d_in, const int* in_sizes, int n_in,
                              void* d_out, int out_size) {
    const float *ent_emb, *rel_emb, *rel_mask, *qe;
    const float *W_tok, *b_tok, *W_key, *b_key, *W_comp, *b_comp;
    const float *Wq, *bq, *Wk, *bk, *Wv, *bv, *W_kg, *b_kg;
    const int *src, *dst, *rel_id;
    if (in_sizes[5] == E_EDG) {
        ent_emb = (const float*)d_in[0];  rel_emb = (const float*)d_in[1];
        rel_mask = (const float*)d_in[3]; qe = (const float*)d_in[4];
        src = (const int*)d_in[5]; dst = (const int*)d_in[6]; rel_id = (const int*)d_in[7];
        W_tok = (const float*)d_in[8];  b_tok = (const float*)d_in[9];
        W_key = (const float*)d_in[10]; b_key = (const float*)d_in[11];
        W_comp = (const float*)d_in[12]; b_comp = (const float*)d_in[13];
        Wq = (const float*)d_in[14]; bq = (const float*)d_in[15];
        Wk = (const float*)d_in[16]; bk = (const float*)d_in[17];
        Wv = (const float*)d_in[18]; bv = (const float*)d_in[19];
        W_kg = (const float*)d_in[20]; b_kg = (const float*)d_in[21];
    } else {
        ent_emb = (const float*)d_in[0];  rel_emb = (const float*)d_in[1];
        rel_mask = (const float*)d_in[3]; qe = (const float*)d_in[4];
        W_tok = (const float*)d_in[5];  b_tok = (const float*)d_in[6];
        W_key = (const float*)d_in[7];  b_key = (const float*)d_in[8];
        W_comp = (const float*)d_in[9]; b_comp = (const float*)d_in[10];
        Wq = (const float*)d_in[11]; bq = (const float*)d_in[12];
        Wk = (const float*)d_in[13]; bk = (const float*)d_in[14];
        Wv = (const float*)d_in[15]; bv = (const float*)d_in[16];
        W_kg = (const float*)d_in[17]; b_kg = (const float*)d_in[18];
        src = (const int*)d_in[19]; dst = (const int*)d_in[20]; rel_id = (const int*)d_in[21];
    }
    float* out = (float*)d_out;

    k_zero<<<(B_DIM * N_ENTC * H_DIM + 255) / 256, 256>>>(Wq, bq, Wk, bk, Wv, bv);
    k_qbar<<<B_DIM, 128>>>(qe, W_tok, b_tok);
    k_edge<<<E_EDG / 16, 128>>>(ent_emb, rel_emb, rel_mask, src, dst, rel_id,
                                 W_key, b_key, W_comp, b_comp);
    k_w<<<E_EDG / 8, 256>>>();
    k_attsm<<<B_DIM, 1024>>>();
    k_m1<<<(B_DIM * E_EDG + 255) / 256, 256>>>(src);
    k_m2<<<(B_DIM * E_EDG + 255) / 256, 256>>>(src);
    k_msg<<<E_EDG, 128>>>(src, dst);
    k_ln<<<NROWS / 16, 128>>>();
    {
        dim3 g(6, NROWS / 128);
        k_qkv_tc<<<g, 256>>>();
    }
    {
        dim3 g((N_ENTC + 63) / 64, (N_ENTC + 127) / 128, B_DIM);
        k_scores_tc<<<g, 256>>>();
    }
    k_rowsm<<<B_DIM * N_ENTC, 256>>>();
    {
        dim3 g((N_ENTC + 255) / 256, NCHUNK, B_DIM);
        k_imp_part<<<g, 256>>>();
    }
    {
        dim3 g((N_ENTC + 255) / 256, B_DIM);
        k_topk<<<g, 256>>>();
    }
    {
        dim3 g((KSEL + 63) / 64, B_DIM);
        k_attend_sel<<<g, 256>>>();
    }
    {
        dim3 g((KSEL + 15) / 16, B_DIM);
        k_sel<<<g, 128>>>(W_kg, b_kg, out);
    }
}

// round 16
// speedup vs baseline: 1.1065x; 1.0450x over previous
#include <cuda_runtime.h>
#include <math.h>
#include <stdint.h>

#define N_ENTC 1968
#define E_EDG  20000
#define S_DIM  16
#define D2H    256
#define H_DIM  128
#define B_DIM  8
#define T_DIM  20
#define KSEL   196
#define NCHUNK 8
#define NC_LEN 246
#define NROWS  (B_DIM * N_ENTC)
#define UPITCH 260
#define EPB    8
#define SQRT_H 11.313708498984761f

__device__ float    g_qbar[B_DIM * H_DIM];
__device__ float    g_kbar[(size_t)E_EDG * H_DIM];
__device__ float    g_cf[(size_t)E_EDG * H_DIM];
__device__ float    g_w[(size_t)B_DIM * E_EDG];
__device__ float    g_att[(size_t)B_DIM * E_EDG];
__device__ unsigned g_m1[B_DIM * N_ENTC];
__device__ unsigned g_m2[B_DIM * N_ENTC];
__device__ float    g_neigh[(size_t)B_DIM * N_ENTC * H_DIM];
__device__ float    g_X[(size_t)NROWS * H_DIM];
__device__ float    g_Wt[3 * H_DIM * H_DIM];
__device__ float    g_Wb[3 * H_DIM];
__device__ float    g_Q[(size_t)B_DIM * N_ENTC * H_DIM];
__device__ float    g_Kt[(size_t)B_DIM * N_ENTC * H_DIM];
__device__ float    g_V[(size_t)B_DIM * N_ENTC * H_DIM];
__device__ float    g_P[(size_t)B_DIM * N_ENTC * N_ENTC];
__device__ float    g_attend[(size_t)B_DIM * KSEL * H_DIM];
__device__ double   g_imp_part[(size_t)B_DIM * NCHUNK * N_ENTC];
__device__ int      g_idx[B_DIM * KSEL];

// fused: zero neigh/m1/m2 + transpose QKV weights + stage biases
__global__ void k_zero(const float* __restrict__ Wq, const float* __restrict__ bq,
                       const float* __restrict__ Wk, const float* __restrict__ bk,
                       const float* __restrict__ Wv, const float* __restrict__ bv) {
    int i = blockIdx.x * 256 + threadIdx.x;
    if (i < B_DIM * N_ENTC * H_DIM) g_neigh[i] = 0.f;
    if (i < B_DIM * N_ENTC) { g_m1[i] = 0u; g_m2[i] = 0u; }
    if (i < 3 * H_DIM * H_DIM) {
        int which = i >> 14, r = i & 16383;
        int c = r >> 7, k = r & 127;
        const float* W = (which == 0) ? Wq : (which == 1) ? Wk : Wv;
        g_Wt[i] = W[k * H_DIM + c];
    }
    if (i < 3 * H_DIM) {
        int which = i >> 7, c = i & 127;
        const float* bb = (which == 0) ? bq : (which == 1) ? bk : bv;
        g_Wb[i] = bb[c];
    }
}

// qbar[b] = (mean_t question[b]) @ W_tok + b_tok
__global__ void k_qbar(const float* __restrict__ qe, const float* __restrict__ W_tok,
                       const float* __restrict__ b_tok) {
    __shared__ float qs[D2H];
    int b = blockIdx.x, tid = threadIdx.x;  // 128 thr
    #pragma unroll
    for (int k = 0; k < 2; k++) {
        int d = tid + 128 * k;
        float s = 0.f;
        #pragma unroll
        for (int t = 0; t < T_DIM; t++) s += qe[((size_t)b * T_DIM + t) * D2H + d];
        qs[d] = s * (1.f / (float)T_DIM);
    }
    __syncthreads();
    float acc = b_tok[tid];
    #pragma unroll 4
    for (int d = 0; d < D2H; d++) acc += qs[d] * W_tok[d * H_DIM + tid];
    g_qbar[b * H_DIM + tid] = acc;
}

// per-edge kernel, 8 edges/block (half smem+regs -> ~2x occupancy).
// Per-(e,d) phase-1 order and per-(e,tid) phase-2 d-order unchanged -> bit-identical kbar/cf.
__global__ void k_edge(const float* __restrict__ ent_emb, const float* __restrict__ rel_emb,
                       const float* __restrict__ rel_mask, const int* __restrict__ src,
                       const int* __restrict__ dst, const int* __restrict__ rel_id,
                       const float* __restrict__ W_key, const float* __restrict__ b_key,
                       const float* __restrict__ W_comp, const float* __restrict__ b_comp) {
    __shared__ __align__(16) float s_u[EPB * UPITCH];
    __shared__ __align__(16) float s_v[EPB * UPITCH];
    __shared__ float s_mask[EPB][S_DIM];
    __shared__ float s_eps[EPB], s_msum[EPB];
    __shared__ int   s_src[EPB], s_dst[EPB], s_rid[EPB];
    __shared__ float s_wc[S_DIM];
    int tid = threadIdx.x;  // 128 thr
    int e0  = blockIdx.x * EPB;
    if (tid < EPB) { s_src[tid] = src[e0+tid]; s_dst[tid] = dst[e0+tid]; s_rid[tid] = rel_id[e0+tid]; }
    if (tid >= 32 && tid < 32 + S_DIM) s_wc[tid - 32] = W_comp[tid - 32];
    __syncthreads();
    if (tid < EPB * S_DIM) {
        int e = tid / S_DIM, s = tid % S_DIM;
        s_mask[e][s] = rel_mask[s_rid[e] * S_DIM + s];
    }
    __syncthreads();
    if (tid < EPB) {
        float cnt = 0.f, ms = 0.f;
        #pragma unroll
        for (int s = 0; s < S_DIM; s++) { float m = s_mask[tid][s]; ms += m; cnt += (m != 0.f) ? 1.f : 0.f; }
        s_eps[tid]  = (cnt == 0.f) ? 1.f : cnt;
        s_msum[tid] = ms;
    }
    __syncthreads();
    // phase 1: 4 iterations x 2 edges; thread -> (edge half, float4 over d)
    #pragma unroll 1
    for (int it = 0; it < EPB / 2; it++) {
        int e = it * 2 + (tid >> 6);
        int f = tid & 63;
        const float4* ps = (const float4*)(ent_emb + (size_t)s_src[e] * (S_DIM * D2H));
        const float4* pd = (const float4*)(ent_emb + (size_t)s_dst[e] * (S_DIM * D2H));
        const float4* pr = (const float4*)(rel_emb + (size_t)s_rid[e] * (S_DIM * D2H));
        float4 au = make_float4(0.f, 0.f, 0.f, 0.f);
        float4 av = make_float4(0.f, 0.f, 0.f, 0.f);
        #pragma unroll
        for (int s = 0; s < S_DIM; s++) {
            float4 a = ps[s * 64 + f], r = pr[s * 64 + f], dd = pd[s * 64 + f];
            float cx = (a.x + r.x) - dd.x;
            float cy = (a.y + r.y) - dd.y;
            float cz = (a.z + r.z) - dd.z;
            float cw = (a.w + r.w) - dd.w;
            float m = s_mask[e][s], wv = s_wc[s];
            au.x += m * cx; au.y += m * cy; au.z += m * cz; au.w += m * cw;
            av.x += wv * cx; av.y += wv * cy; av.z += wv * cz; av.w += wv * cw;
        }
        *(float4*)(s_u + e * UPITCH + 4 * f) = au;
        *(float4*)(s_v + e * UPITCH + 4 * f) = av;
    }
    __syncthreads();
    float wcsum = 0.f;
    #pragma unroll
    for (int s = 0; s < S_DIM; s++) wcsum += s_wc[s];
    float ak[EPB], ac[EPB];
    #pragma unroll
    for (int e = 0; e < EPB; e++) { ak[e] = 0.f; ac[e] = 0.f; }
    #pragma unroll 2
    for (int dc = 0; dc < D2H; dc += 4) {
        float w0 = W_key[(dc + 0) * H_DIM + tid];
        float w1 = W_key[(dc + 1) * H_DIM + tid];
        float w2 = W_key[(dc + 2) * H_DIM + tid];
        float w3 = W_key[(dc + 3) * H_DIM + tid];
        #pragma unroll
        for (int e = 0; e < EPB; e++) {
            float4 uu = *(const float4*)(s_u + e * UPITCH + dc);
            ak[e] += uu.x * w0; ak[e] += uu.y * w1; ak[e] += uu.z * w2; ak[e] += uu.w * w3;
            float4 vv = *(const float4*)(s_v + e * UPITCH + dc);
            ac[e] += vv.x * w0; ac[e] += vv.y * w1; ac[e] += vv.z * w2; ac[e] += vv.w * w3;
        }
    }
    float bk = b_key[tid], bc = b_comp[0];
    #pragma unroll
    for (int e = 0; e < EPB; e++) {
        g_kbar[(size_t)(e0+e) * H_DIM + tid] = (ak[e] + s_msum[e] * bk) / s_eps[e];
        g_cf[(size_t)(e0+e) * H_DIM + tid]   = ac[e] + wcsum * bk + bc;
    }
}

// w[b,e] = 0.125 * qbar[b] . kbar[e]
__global__ void k_w() {
    __shared__ float sq[B_DIM * H_DIM];
    int tid = threadIdx.x;  // 256 thr
    for (int i = tid; i < B_DIM * H_DIM; i += 256) sq[i] = g_qbar[i];
    __syncthreads();
    int warp = tid >> 5, lane = tid & 31;
    int e = blockIdx.x * 8 + warp;
    const float* kb = g_kbar + (size_t)e * H_DIM;
    float k0 = kb[lane], k1 = kb[lane+32], k2 = kb[lane+64], k3 = kb[lane+96];
    #pragma unroll
    for (int b = 0; b < B_DIM; b++) {
        const float* q = sq + b * H_DIM;
        float p = q[lane]*k0 + q[lane+32]*k1 + q[lane+64]*k2 + q[lane+96]*k3;
        #pragma unroll
        for (int o = 16; o; o >>= 1) p += __shfl_xor_sync(0xffffffffu, p, o);
        if (lane == 0) g_w[(size_t)b * E_EDG + e] = 0.125f * p;
    }
}

__global__ void k_attsm() {
    int b = blockIdx.x, tid = threadIdx.x;  // 1024 thr
    __shared__ float shm[32];
    __shared__ float s_mx, s_sum;
    const float* wr = g_w + (size_t)b * E_EDG;
    float mx = -INFINITY;
    for (int e = tid; e < E_EDG; e += 1024) mx = fmaxf(mx, wr[e]);
    #pragma unroll
    for (int o = 16; o; o >>= 1) mx = fmaxf(mx, __shfl_xor_sync(0xffffffffu, mx, o));
    if ((tid & 31) == 0) shm[tid >> 5] = mx;
    __syncthreads();
    if (tid == 0) { float v = shm[0]; for (int w = 1; w < 32; w++) v = fmaxf(v, shm[w]); s_mx = v; }
    __syncthreads();
    float M = s_mx, sum = 0.f;
    for (int e = tid; e < E_EDG; e += 1024) sum += expf(wr[e] - M);
    #pragma unroll
    for (int o = 16; o; o >>= 1) sum += __shfl_xor_sync(0xffffffffu, sum, o);
    if ((tid & 31) == 0) shm[tid >> 5] = sum;
    __syncthreads();
    if (tid == 0) { float v = 0.f; for (int w = 0; w < 32; w++) v += shm[w]; s_sum = v; }
    __syncthreads();
    float inv = 1.f / s_sum;
    for (int e = tid; e < E_EDG; e += 1024) g_att[(size_t)b * E_EDG + e] = expf(wr[e] - M) * inv;
}

__global__ void k_m1(const int* __restrict__ src) {
    int i = blockIdx.x * 256 + threadIdx.x;
    if (i >= B_DIM * E_EDG) return;
    int b = i / E_EDG, e = i % E_EDG;
    atomicMax(&g_m1[b * N_ENTC + src[e]], __float_as_uint(g_att[i]));
}
__global__ void k_m2(const int* __restrict__ src) {
    int i = blockIdx.x * 256 + threadIdx.x;
    if (i >= B_DIM * E_EDG) return;
    int b = i / E_EDG, e = i % E_EDG;
    unsigned v = __float_as_uint(g_att[i]);
    if (v != g_m1[b * N_ENTC + src[e]]) atomicMax(&g_m2[b * N_ENTC + src[e]], v);
}

__global__ void k_msg(const int* __restrict__ src, const int* __restrict__ dst) {
    int e = blockIdx.x, h = threadIdx.x;  // 128 thr
    float cf = g_cf[(size_t)e * H_DIM + h];
    int sn = src[e], dn = dst[e];
    #pragma unroll
    for (int b = 0; b < B_DIM; b++) {
        float a  = g_att[(size_t)b * E_EDG + e];
        float m2 = __uint_as_float(g_m2[b * N_ENTC + sn]);
        if (a >= m2) atomicAdd(&g_neigh[((size_t)b * N_ENTC + dn) * H_DIM + h], cf * a);
    }
}

// LayerNorm (bit-identical), writes g_X
__global__ void k_ln() {
    __shared__ float sx[16][H_DIM];
    int tid = threadIdx.x;  // 128 thr
    size_t r0 = (size_t)blockIdx.x * 16;
    for (int i = tid; i < 16 * H_DIM; i += 128) ((float*)sx)[i] = g_neigh[r0 * H_DIM + i];
    __syncthreads();
    int warp = tid >> 5, lane = tid & 31;
    #pragma unroll
    for (int j = 0; j < 4; j++) {
        int r = warp * 4 + j;
        float x0 = sx[r][lane], x1 = sx[r][lane+32], x2 = sx[r][lane+64], x3 = sx[r][lane+96];
        float s = x0 + x1 + x2 + x3;
        #pragma unroll
        for (int o = 16; o; o >>= 1) s += __shfl_xor_sync(0xffffffffu, s, o);
        float mu = s * (1.f / 128.f);
        float d0 = x0-mu, d1 = x1-mu, d2 = x2-mu, d3 = x3-mu;
        float q = d0*d0 + d1*d1 + d2*d2 + d3*d3;
        #pragma unroll
        for (int o = 16; o; o >>= 1) q += __shfl_xor_sync(0xffffffffu, q, o);
        float rs = rsqrtf(q * (1.f / 128.f) + 1e-5f);
        sx[r][lane] = d0*rs; sx[r][lane+32] = d1*rs; sx[r][lane+64] = d2*rs; sx[r][lane+96] = d3*rs;
    }
    __syncthreads();
    for (int i = tid; i < 16 * H_DIM; i += 128) g_X[r0 * H_DIM + i] = ((float*)sx)[i];
}

// ---------------- shared TF32 machinery ----------------
#define MMA_TF32(c, a0, a1, a2, a3, b0, b1)                                   \
    asm volatile(                                                             \
        "mma.sync.aligned.m16n8k8.row.col.f32.tf32.tf32.f32 "                 \
        "{%0,%1,%2,%3}, {%4,%5,%6,%7}, {%8,%9}, {%0,%1,%2,%3};"               \
        : "+f"(c[0]), "+f"(c[1]), "+f"(c[2]), "+f"(c[3])                      \
        : "r"(a0), "r"(a1), "r"(a2), "r"(a3), "r"(b0), "r"(b1))

__device__ __forceinline__ void tf32_split(float x, uint32_t& h, uint32_t& l) {
    asm("cvt.rna.tf32.f32 %0, %1;" : "=r"(h) : "f"(x));
    float r = x - __uint_as_float(h);
    asm("cvt.rna.tf32.f32 %0, %1;" : "=r"(l) : "f"(r));
}

__device__ __forceinline__ void cp16(uint32_t dst, const void* src, bool valid) {
    int sz = valid ? 16 : 0;
    asm volatile("cp.async.cg.shared.global [%0], [%1], 16, %2;"
                 :: "r"(dst), "l"(src), "r"(sz));
}
#define CP_COMMIT() asm volatile("cp.async.commit_group;")
#define CP_WAIT1()  asm volatile("cp.async.wait_group 1;" ::: "memory")
#define CP_WAIT0()  asm volatile("cp.async.wait_group 0;" ::: "memory")
#define PHI(kk) (((kk) & 8) | (((kk) & 3) << 1) | (((kk) >> 2) & 1))

__device__ __forceinline__ void tc_gemm_core(
    const float* __restrict__ Arows, const float* __restrict__ Brows,
    bool av0, bool av1, bool bv,
    int arow0_off, int arow1_off, int brow_off,
    float (&acc)[8][4],
    float* sQ0, float* sQ1,
    uint32_t* Kh0, uint32_t* Kl0, uint32_t* Kh1, uint32_t* Kl1)
{
    int tid = threadIdx.x;
    int warp = tid >> 5, lane = tid & 31;
    int g = lane >> 2, tig = lane & 3;
    int mr = warp * 16;
    int qrow0 = tid >> 2, seg = tid & 3;
    float* sQb[2]  = { sQ0, sQ1 };
    uint32_t* Khb[2] = { Kh0, Kh1 };
    uint32_t* Klb[2] = { Kl0, Kl1 };
    uint32_t qd0[2], qd1[2];
    #pragma unroll
    for (int bf = 0; bf < 2; bf++) {
        qd0[bf] = (uint32_t)__cvta_generic_to_shared(&sQb[bf][qrow0 * 20 + seg * 4]);
        qd1[bf] = (uint32_t)__cvta_generic_to_shared(&sQb[bf][(qrow0 + 64) * 20 + seg * 4]);
    }
    const float* qsrc0 = Arows + arow0_off;
    const float* qsrc1 = Arows + arow1_off;
    const float* ksrc  = Brows + brow_off;

    cp16(qd0[0], qsrc0, av0);
    cp16(qd1[0], qsrc1, av1);
    CP_COMMIT();
    {
        float4 kr = bv ? *(const float4*)ksrc : make_float4(0.f,0.f,0.f,0.f);
        float kvv[4] = {kr.x, kr.y, kr.z, kr.w};
        int row = tid >> 2;
        #pragma unroll
        for (int i = 0; i < 4; i++) {
            uint32_t h, l; tf32_split(kvv[i], h, l);
            int kk = seg * 4 + i;
            Khb[0][row * 20 + PHI(kk)] = h;
            Klb[0][row * 20 + PHI(kk)] = l;
        }
    }

    #pragma unroll 1
    for (int c = 0; c < 8; c++) {
        int buf = c & 1;
        float4 kr;
        if (c < 7) {
            int kc = (c + 1) * 16;
            cp16(qd0[buf ^ 1], qsrc0 + kc, av0);
            cp16(qd1[buf ^ 1], qsrc1 + kc, av1);
            CP_COMMIT();
            kr = bv ? *(const float4*)(ksrc + kc) : make_float4(0.f,0.f,0.f,0.f);
            CP_WAIT1();
        } else {
            CP_WAIT0();
        }
        __syncthreads();
        const float* Qs = sQb[buf];
        const uint32_t* KH = Khb[buf];
        const uint32_t* KL = Klb[buf];
        #pragma unroll
        for (int ks = 0; ks < 2; ks++) {
            int kb = ks * 8;
            float fa0 = Qs[(mr + g)     * 20 + kb + tig];
            float fa1 = Qs[(mr + g + 8) * 20 + kb + tig];
            float fa2 = Qs[(mr + g)     * 20 + kb + tig + 4];
            float fa3 = Qs[(mr + g + 8) * 20 + kb + tig + 4];
            uint32_t ah0, al0, ah1, al1, ah2, al2, ah3, al3;
            tf32_split(fa0, ah0, al0); tf32_split(fa1, ah1, al1);
            tf32_split(fa2, ah2, al2); tf32_split(fa3, ah3, al3);
            #pragma unroll
            for (int nt = 0; nt < 8; nt++) {
                uint2 bh = *(const uint2*)&KH[(nt * 8 + g) * 20 + kb + 2 * tig];
                uint2 bl = *(const uint2*)&KL[(nt * 8 + g) * 20 + kb + 2 * tig];
                MMA_TF32(acc[nt], al0, al1, al2, al3, bh.x, bh.y);
                MMA_TF32(acc[nt], ah0, ah1, ah2, ah3, bl.x, bl.y);
                MMA_TF32(acc[nt], ah0, ah1, ah2, ah3, bh.x, bh.y);
            }
        }
        if (c < 7) {
            int nb = buf ^ 1;
            float kvv[4] = {kr.x, kr.y, kr.z, kr.w};
            int row = tid >> 2;
            #pragma unroll
            for (int i = 0; i < 4; i++) {
                uint32_t h, l; tf32_split(kvv[i], h, l);
                int kk = seg * 4 + i;
                Khb[nb][row * 20 + PHI(kk)] = h;
                Klb[nb][row * 20 + PHI(kk)] = l;
            }
        }
        __syncthreads();
    }
}

// scores: P = sqrt(H) * Q @ K^T
__global__ void __launch_bounds__(256) k_scores_tc() {
    __shared__ __align__(16) float sQ[2][128 * 20];
    __shared__ __align__(16) uint32_t Kh[2][64 * 20], Kl[2][64 * 20];
    int b = blockIdx.z;
    int r0 = blockIdx.y * 128, c0 = blockIdx.x * 64;
    int tid = threadIdx.x;
    int warp = tid >> 5, lane = tid & 31;
    int g = lane >> 2, tig = lane & 3;
    int mr = warp * 16;
    const float* Qb = g_Q  + (size_t)b * N_ENTC * H_DIM;
    const float* Kb = g_Kt + (size_t)b * N_ENTC * H_DIM;
    int qrow0 = tid >> 2, seg = tid & 3;
    bool av0 = (r0 + qrow0) < N_ENTC;
    bool av1 = (r0 + qrow0 + 64) < N_ENTC;
    bool bv  = (c0 + qrow0) < N_ENTC;
    int a0off = (av0 ? (r0 + qrow0)      : 0) * H_DIM + seg * 4;
    int a1off = (av1 ? (r0 + qrow0 + 64) : 0) * H_DIM + seg * 4;
    int boff  = (bv  ? (c0 + qrow0)      : 0) * H_DIM + seg * 4;
    float acc[8][4];
    #pragma unroll
    for (int nt = 0; nt < 8; nt++)
        #pragma unroll
        for (int j = 0; j < 4; j++) acc[nt][j] = 0.f;
    tc_gemm_core(Qb, Kb, av0, av1, bv, a0off, a1off, boff, acc,
                 sQ[0], sQ[1], Kh[0], Kl[0], Kh[1], Kl[1]);
    #pragma unroll
    for (int nt = 0; nt < 8; nt++) {
        int col = c0 + nt * 8 + 2 * tig;
        int row_a = r0 + mr + g, row_b = r0 + mr + g + 8;
        if (row_a < N_ENTC) {
            float* pr = g_P + ((size_t)b * N_ENTC + row_a) * N_ENTC;
            if (col < N_ENTC)     pr[col]     = acc[nt][0] * SQRT_H;
            if (col + 1 < N_ENTC) pr[col + 1] = acc[nt][1] * SQRT_H;
        }
        if (row_b < N_ENTC) {
            float* pr = g_P + ((size_t)b * N_ENTC + row_b) * N_ENTC;
            if (col < N_ENTC)     pr[col]     = acc[nt][2] * SQRT_H;
            if (col + 1 < N_ENTC) pr[col + 1] = acc[nt][3] * SQRT_H;
        }
    }
}

// QKV projection via TC
__global__ void __launch_bounds__(256) k_qkv_tc() {
    __shared__ __align__(16) float sQ[2][128 * 20];
    __shared__ __align__(16) uint32_t Kh[2][64 * 20], Kl[2][64 * 20];
    int which = blockIdx.x >> 1;
    int c0 = (blockIdx.x & 1) * 64;
    int r0 = blockIdx.y * 128;
    int tid = threadIdx.x;
    int warp = tid >> 5, lane = tid & 31;
    int g = lane >> 2, tig = lane & 3;
    int mr = warp * 16;
    const float* Wt = g_Wt + which * H_DIM * H_DIM;
    int qrow0 = tid >> 2, seg = tid & 3;
    int a0off = (r0 + qrow0) * H_DIM + seg * 4;
    int a1off = (r0 + qrow0 + 64) * H_DIM + seg * 4;
    int boff  = (c0 + qrow0) * H_DIM + seg * 4;
    float acc[8][4];
    #pragma unroll
    for (int nt = 0; nt < 8; nt++)
        #pragma unroll
        for (int j = 0; j < 4; j++) acc[nt][j] = 0.f;
    tc_gemm_core(g_X, Wt, true, true, true, a0off, a1off, boff, acc,
                 sQ[0], sQ[1], Kh[0], Kl[0], Kh[1], Kl[1]);
    float* outp = (which == 0) ? g_Q : (which == 1) ? g_Kt : g_V;
    #pragma unroll
    for (int nt = 0; nt < 8; nt++) {
        int col = c0 + nt * 8 + 2 * tig;
        float b0 = g_Wb[which * H_DIM + col];
        float b1 = g_Wb[which * H_DIM + col + 1];
        int row_a = r0 + mr + g, row_b = r0 + mr + g + 8;
        outp[(size_t)row_a * H_DIM + col]     = acc[nt][0] + b0;
        outp[(size_t)row_a * H_DIM + col + 1] = acc[nt][1] + b1;
        outp[(size_t)row_b * H_DIM + col]     = acc[nt][2] + b0;
        outp[(size_t)row_b * H_DIM + col + 1] = acc[nt][3] + b1;
    }
}

// row softmax: single expf pass; P loaded evict-first (streaming)
__global__ void k_rowsm() {
    __shared__ __align__(16) float srow[N_ENTC];
    __shared__ float shm[8];
    __shared__ float s_mx, s_sum;
    size_t bn = blockIdx.x;
    float* row = g_P + bn * N_ENTC;
    int tid = threadIdx.x;  // 256 thr
    for (int i = tid; i < N_ENTC / 4; i += 256)
        ((float4*)srow)[i] = __ldcs((const float4*)row + i);
    __syncthreads();
    float mx = -INFINITY;
    for (int m = tid; m < N_ENTC; m += 256) mx = fmaxf(mx, srow[m]);
    #pragma unroll
    for (int o = 16; o; o >>= 1) mx = fmaxf(mx, __shfl_xor_sync(0xffffffffu, mx, o));
    if ((tid & 31) == 0) shm[tid >> 5] = mx;
    __syncthreads();
    if (tid == 0) { float v = shm[0]; for (int w = 1; w < 8; w++) v = fmaxf(v, shm[w]); s_mx = v; }
    __syncthreads();
    float M = s_mx, sum = 0.f;
    for (int m = tid; m < N_ENTC; m += 256) {
        float t = expf(srow[m] - M);
        srow[m] = t;
        sum += t;
    }
    #pragma unroll
    for (int o = 16; o; o >>= 1) sum += __shfl_xor_sync(0xffffffffu, sum, o);
    if ((tid & 31) == 0) shm[tid >> 5] = sum;
    __syncthreads();
    if (tid == 0) { float v = 0.f; for (int w = 0; w < 8; w++) v += shm[w]; s_sum = v; }
    __syncthreads();
    float inv = 1.f / s_sum;
    for (int m = tid; m < N_ENTC; m += 256) row[m] = srow[m] * inv;
}

// importance stage 1: partial double sums; P read evict-first (streaming)
__global__ void k_imp_part() {
    int m = blockIdx.x * 256 + threadIdx.x;
    int nc = blockIdx.y, b = blockIdx.z;
    if (m >= N_ENTC) return;
    const float* base = g_P + (size_t)b * N_ENTC * N_ENTC + m;
    int n0 = nc * NC_LEN, n1 = n0 + NC_LEN;
    double a0 = 0.0, a1 = 0.0, a2 = 0.0, a3 = 0.0;
    int n = n0;
    for (; n + 4 <= n1; n += 4) {
        a0 += (double)__ldcs(base + (size_t)(n+0) * N_ENTC);
        a1 += (double)__ldcs(base + (size_t)(n+1) * N_ENTC);
        a2 += (double)__ldcs(base + (size_t)(n+2) * N_ENTC);
        a3 += (double)__ldcs(base + (size_t)(n+3) * N_ENTC);
    }
    for (; n < n1; n++) a0 += (double)__ldcs(base + (size_t)n * N_ENTC);
    g_imp_part[((size_t)b * NCHUNK + nc) * N_ENTC + m] = (a0 + a1) + (a2 + a3);
}

// importance stage 2 + top-K rank
__global__ void k_topk() {
    __shared__ float sv[N_ENTC];
    int b = blockIdx.y, tid = threadIdx.x;  // 256 thr
    const double* pp = g_imp_part + (size_t)b * NCHUNK * N_ENTC;
    for (int m = tid; m < N_ENTC; m += 256) {
        double s = 0.0;
        #pragma unroll
        for (int c = 0; c < NCHUNK; c++) s += pp[(size_t)c * N_ENTC + m];
        sv[m] = (float)(s * (1.0 / (double)N_ENTC));
    }
    __syncthreads();
    int m = blockIdx.x * 256 + tid;
    if (m >= N_ENTC) return;
    float vm = sv[m];
    int rank = 0;
    for (int n = 0; n < N_ENTC; n++) {
        float vn = sv[n];
        rank += (vn > vm) ? 1 : 0;
        rank += (vn == vm && n < m) ? 1 : 0;
    }
    if (rank < KSEL) g_idx[b * KSEL + rank] = m;
}

// attended rows for selected indices
__global__ void k_attend_sel() {
    __shared__ __align__(16) float sP[32][68];
    __shared__ __align__(16) float sV[32][132];
    __shared__ int s_idx[64];
    int b = blockIdx.y;
    int r0 = blockIdx.x * 64;
    int tid = threadIdx.x, tx = tid & 15, ty = tid >> 4;  // 256 thr
    if (tid < 64) {
        int sr = r0 + tid;
        s_idx[tid] = (sr < KSEL) ? g_idx[b * KSEL + sr] : 0;
    }
    __syncthreads();
    const float* Pb = g_P + (size_t)b * N_ENTC * N_ENTC;
    const float* Vb = g_V + (size_t)b * N_ENTC * H_DIM;
    float acc[2][4][4];
    #pragma unroll
    for (int h = 0; h < 2; h++)
        #pragma unroll
        for (int i = 0; i < 4; i++)
            #pragma unroll
            for (int j = 0; j < 4; j++) acc[h][i][j] = 0.f;
    for (int k0 = 0; k0 < N_ENTC; k0 += 32) {
        #pragma unroll
        for (int p = 0; p < 8; p++) {
            int lin = tid + 256 * p;
            int kk = lin & 31, row = lin >> 5;
            int gk = k0 + kk;
            bool rv = (r0 + row) < KSEL;
            sP[kk][row] = (rv && gk < N_ENTC) ? Pb[(size_t)s_idx[row] * N_ENTC + gk] : 0.f;
        }
        #pragma unroll
        for (int p = 0; p < 16; p++) {
            int lin = tid + 256 * p;
            int col = lin & 127, kk2 = lin >> 7;
            int gk2 = k0 + kk2;
            sV[kk2][col] = (gk2 < N_ENTC) ? Vb[(size_t)gk2 * H_DIM + col] : 0.f;
        }
        __syncthreads();
        #pragma unroll
        for (int kk = 0; kk < 32; kk++) {
            float4 a = *(const float4*)&sP[kk][ty * 4];
            float ar[4] = {a.x, a.y, a.z, a.w};
            #pragma unroll
            for (int h = 0; h < 2; h++) {
                float4 bb = *(const float4*)&sV[kk][h * 64 + tx * 4];
                float br[4] = {bb.x, bb.y, bb.z, bb.w};
                #pragma unroll
                for (int i = 0; i < 4; i++)
                    #pragma unroll
                    for (int j = 0; j < 4; j++) acc[h][i][j] += ar[i] * br[j];
            }
        }
        __syncthreads();
    }
    #pragma unroll
    for (int h = 0; h < 2; h++)
        #pragma unroll
        for (int i = 0; i < 4; i++) {
            int gr = r0 + ty * 4 + i;
            if (gr >= KSEL) continue;
            #pragma unroll
            for (int j = 0; j < 4; j++) {
                int gc = h * 64 + tx * 4 + j;
                g_attend[((size_t)b * KSEL + gr) * H_DIM + gc] = acc[h][i][j];
            }
        }
}

// out[b,k,:] = tanh(attend_compact[b,k,:] @ W_kg + b_kg)
__global__ void k_sel(const float* __restrict__ W_kg, const float* __restrict__ b_kg,
                      float* __restrict__ out) {
    __shared__ float sx[16][H_DIM];
    int tid = threadIdx.x;  // 128 thr
    int b = blockIdx.y;
    int kt = blockIdx.x * 16;
    int nvalid = min(16, KSEL - kt);
    for (int r = 0; r < nvalid; r++)
        sx[r][tid] = g_attend[((size_t)b * KSEL + kt + r) * H_DIM + tid];
    __syncthreads();
    float acc[16];
    #pragma unroll
    for (int r = 0; r < 16; r++) acc[r] = 0.f;
    #pragma unroll 2
    for (int d = 0; d < H_DIM; d++) {
        float w = W_kg[d * H_DIM + tid];
        #pragma unroll
        for (int r = 0; r < 16; r++) acc[r] += sx[r][d] * w;
    }
    float bb = b_kg[tid];
    for (int r = 0; r < nvalid; r++)
        out[((size_t)b * KSEL + kt + r) * H_DIM + tid] = tanhf(acc[r] + bb);
}

extern "C" void kernel_launch(void* const* d_in, const int* in_sizes, int n_in,
                              void* d_out, int out_size) {
    const float *ent_emb, *rel_emb, *rel_mask, *qe;
    const float *W_tok, *b_tok, *W_key, *b_key, *W_comp, *b_comp;
    const float *Wq, *bq, *Wk, *bk, *Wv, *bv, *W_kg, *b_kg;
    const int *src, *dst, *rel_id;
    if (in_sizes[5] == E_EDG) {
        ent_emb = (const float*)d_in[0];  rel_emb = (const float*)d_in[1];
        rel_mask = (const float*)d_in[3]; qe = (const float*)d_in[4];
        src = (const int*)d_in[5]; dst = (const int*)d_in[6]; rel_id = (const int*)d_in[7];
        W_tok = (const float*)d_in[8];  b_tok = (const float*)d_in[9];
        W_key = (const float*)d_in[10]; b_key = (const float*)d_in[11];
        W_comp = (const float*)d_in[12]; b_comp = (const float*)d_in[13];
        Wq = (const float*)d_in[14]; bq = (const float*)d_in[15];
        Wk = (const float*)d_in[16]; bk = (const float*)d_in[17];
        Wv = (const float*)d_in[18]; bv = (const float*)d_in[19];
        W_kg = (const float*)d_in[20]; b_kg = (const float*)d_in[21];
    } else {
        ent_emb = (const float*)d_in[0];  rel_emb = (const float*)d_in[1];
        rel_mask = (const float*)d_in[3]; qe = (const float*)d_in[4];
        W_tok = (const float*)d_in[5];  b_tok = (const float*)d_in[6];
        W_key = (const float*)d_in[7];  b_key = (const float*)d_in[8];
        W_comp = (const float*)d_in[9]; b_comp = (const float*)d_in[10];
        Wq = (const float*)d_in[11]; bq = (const float*)d_in[12];
        Wk = (const float*)d_in[13]; bk = (const float*)d_in[14];
        Wv = (const float*)d_in[15]; bv = (const float*)d_in[16];
        W_kg = (const float*)d_in[17]; b_kg = (const float*)d_in[18];
        src = (const int*)d_in[19]; dst = (const int*)d_in[20]; rel_id = (const int*)d_in[21];
    }
    float* out = (float*)d_out;

    k_zero<<<(B_DIM * N_ENTC * H_DIM + 255) / 256, 256>>>(Wq, bq, Wk, bk, Wv, bv);
    k_qbar<<<B_DIM, 128>>>(qe, W_tok, b_tok);
    k_edge<<<E_EDG / EPB, 128>>>(ent_emb, rel_emb, rel_mask, src, dst, rel_id,
                                  W_key, b_key, W_comp, b_comp);
    k_w<<<E_EDG / 8, 256>>>();
    k_attsm<<<B_DIM, 1024>>>();
    k_m1<<<(B_DIM * E_EDG + 255) / 256, 256>>>(src);
    k_m2<<<(B_DIM * E_EDG + 255) / 256, 256>>>(src);
    k_msg<<<E_EDG, 128>>>(src, dst);
    k_ln<<<NROWS / 16, 128>>>();
    {
        dim3 g(6, NROWS / 128);
        k_qkv_tc<<<g, 256>>>();
    }
    {
        dim3 g((N_ENTC + 63) / 64, (N_ENTC + 127) / 128, B_DIM);
        k_scores_tc<<<g, 256>>>();
    }
    k_rowsm<<<B_DIM * N_ENTC, 256>>>();
    {
        dim3 g((N_ENTC + 255) / 256, NCHUNK, B_DIM);
        k_imp_part<<<g, 256>>>();
    }
    {
        dim3 g((N_ENTC + 255) / 256, B_DIM);
        k_topk<<<g, 256>>>();
    }
    {
        dim3 g((KSEL + 63) / 64, B_DIM);
        k_attend_sel<<<g, 256>>>();
    }
    {
        dim3 g((KSEL + 15) / 16, B_DIM);
        k_sel<<<g, 128>>>(W_kg, b_kg, out);
    }
}